// round 10
// baseline (speedup 1.0000x reference)
#include <cuda_runtime.h>
#include <cstdint>
#include <cstddef>

#define BB   4
#define NN   1024
#define DIMC 1024
#define HH   16
#define DHD  64

// Scratch (no cudaMalloc allowed)
__device__ float g_Q[(size_t)BB * NN * DIMC];
__device__ float g_K[(size_t)BB * NN * DIMC];
__device__ float g_V[(size_t)BB * NN * DIMC];
__device__ float g_O[(size_t)BB * NN * DIMC];
__device__ float g_Xr[(size_t)BB * NN * DIMC];
__device__ float g_Wqr[(size_t)DIMC * HH * DHD];
__device__ float g_Wkr[(size_t)DIMC * HH * DHD];
__device__ float g_Wvr[(size_t)DIMC * HH * DHD];
__device__ float g_Wor[(size_t)HH * DHD * DIMC];
__device__ float g_inv[(size_t)BB * HH * NN];        // 1/rowsum

__device__ __forceinline__ float tf32r(float x) {
    uint32_t u;
    asm("cvt.rna.tf32.f32 %0, %1;" : "=r"(u) : "f"(x));
    return __uint_as_float(u);
}

__device__ __forceinline__ void cp16(float* smem, const float* gmem) {
    uint32_t s = (uint32_t)__cvta_generic_to_shared(smem);
    asm volatile("cp.async.cg.shared.global [%0], [%1], 16;" :: "r"(s), "l"(gmem));
}
__device__ __forceinline__ void cp_commit() { asm volatile("cp.async.commit_group;"); }
__device__ __forceinline__ void cp_wait1()  { asm volatile("cp.async.wait_group 1;"); }
__device__ __forceinline__ void cp_wait2()  { asm volatile("cp.async.wait_group 2;"); }

#define MMA_TF32(d, a0, a1, a2, a3, b0, b1)                                 \
    asm volatile(                                                           \
        "mma.sync.aligned.m16n8k8.row.col.f32.tf32.tf32.f32 "               \
        "{%0,%1,%2,%3}, {%4,%5,%6,%7}, {%8,%9}, {%0,%1,%2,%3};"             \
        : "+f"(d[0]), "+f"(d[1]), "+f"(d[2]), "+f"(d[3])                    \
        : "r"(a0), "r"(a1), "r"(a2), "r"(a3), "r"(b0), "r"(b1))

// ---------------------------------------------------------------------------
// Pre-round x and all weights to tf32 (rna) once.
// ---------------------------------------------------------------------------
__global__ __launch_bounds__(256) void round_all(
    const float* __restrict__ x,
    const float* __restrict__ Wq, const float* __restrict__ Wk,
    const float* __restrict__ Wv, const float* __restrict__ Wo,
    float* __restrict__ xr,
    float* __restrict__ wqr, float* __restrict__ wkr,
    float* __restrict__ wvr, float* __restrict__ wor)
{
    int i = blockIdx.x * blockDim.x + threadIdx.x;   // float4 index, 2M total
    const float* src; float* dst; int off;
    if (i < (1 << 20)) { src = x; dst = xr; off = i; }
    else {
        int j = i - (1 << 20);
        int w = j >> 18; off = j & ((1 << 18) - 1);
        src = (w == 0) ? Wq : (w == 1) ? Wk : (w == 2) ? Wv : Wo;
        dst = (w == 0) ? wqr : (w == 1) ? wkr : (w == 2) ? wvr : wor;
    }
    float4 v = ((const float4*)src)[off];
    v.x = tf32r(v.x); v.y = tf32r(v.y); v.z = tf32r(v.z); v.w = tf32r(v.w);
    ((float4*)dst)[off] = v;
}

// ---------------------------------------------------------------------------
// tf32 GEMM, 512 threads, 128x128 tile, BK=16, 3-stage cp.async pipeline.
// ---------------------------------------------------------------------------
#define GEMM_SMEM ((3 * 128 * 20 + 3 * 16 * 136) * 4)   // 56832 B

template<bool ROUND_OUT>
__device__ __forceinline__ void gemm_body(
    const float* __restrict__ A, const float* __restrict__ Bm,
    float* __restrict__ C, const float* __restrict__ bias,
    float outScale, int K, int Nc)
{
    extern __shared__ float smg[];
    float* As = smg;                    // [3][128][20]
    float* Bs = smg + 3 * 2560;         // [3][16][136]

    const int t     = threadIdx.x;
    const int wid   = t >> 5, lane = t & 31;
    const int group = lane >> 2, tig = lane & 3;
    const int wm    = (wid & 3) * 32;
    const int wn    = (wid >> 2) * 32;
    const int m0    = blockIdx.y * 128;
    const int n0    = blockIdx.x * 128;

    auto load_stage = [&](int s, int k0) {
        float* Ad = As + s * 2560;
        float* Bd = Bs + s * 2176;
        {
            int r = t >> 2, k4 = (t & 3) * 4;
            cp16(Ad + r * 20 + k4, A + (size_t)(m0 + r) * K + k0 + k4);
        }
        {
            int kr = t >> 5, b4 = (t & 31) * 4;
            cp16(Bd + kr * 136 + (b4 ^ ((kr & 12) << 1)),
                 Bm + (size_t)(k0 + kr) * Nc + n0 + b4);
        }
    };

    float acc[2][4][4] = {};

    load_stage(0, 0);  cp_commit();
    load_stage(1, 16); cp_commit();

    int s = 0;
    for (int k0 = 0; k0 < K; k0 += 16) {
        cp_wait1();
        __syncthreads();
        int s2 = (s >= 1) ? s - 1 : s + 2;
        if (k0 + 32 < K) load_stage(s2, k0 + 32);
        cp_commit();

        const float* Ac = As + s * 2560;
        const float* Bc = Bs + s * 2176;
        #pragma unroll
        for (int ks = 0; ks < 2; ks++) {
            int kk = ks * 8;
            int s0 = kk << 1;
            int s1 = ((kk + 4) & 12) << 1;
            uint32_t a[2][4];
            #pragma unroll
            for (int mf = 0; mf < 2; mf++) {
                int mb = wm + mf * 16;
                a[mf][0] = __float_as_uint(Ac[(mb + group    ) * 20 + kk + tig    ]);
                a[mf][1] = __float_as_uint(Ac[(mb + group + 8) * 20 + kk + tig    ]);
                a[mf][2] = __float_as_uint(Ac[(mb + group    ) * 20 + kk + tig + 4]);
                a[mf][3] = __float_as_uint(Ac[(mb + group + 8) * 20 + kk + tig + 4]);
            }
            #pragma unroll
            for (int nf = 0; nf < 4; nf++) {
                int nb = wn + nf * 8;
                uint32_t b0 = __float_as_uint(Bc[(kk + tig    ) * 136 + ((nb + group) ^ s0)]);
                uint32_t b1 = __float_as_uint(Bc[(kk + tig + 4) * 136 + ((nb + group) ^ s1)]);
                #pragma unroll
                for (int mf = 0; mf < 2; mf++)
                    MMA_TF32(acc[mf][nf], a[mf][0], a[mf][1], a[mf][2], a[mf][3], b0, b1);
            }
        }
        s = (s == 2) ? 0 : s + 1;
        __syncthreads();
    }

    #pragma unroll
    for (int mf = 0; mf < 2; mf++) {
        #pragma unroll
        for (int nf = 0; nf < 4; nf++) {
            int row = m0 + wm + mf * 16 + group;
            int col = n0 + wn + nf * 8 + tig * 2;
            float v0, v1, v2, v3;
            if (ROUND_OUT) {
                v0 = tf32r(acc[mf][nf][0] * outScale);
                v1 = tf32r(acc[mf][nf][1] * outScale);
                v2 = tf32r(acc[mf][nf][2] * outScale);
                v3 = tf32r(acc[mf][nf][3] * outScale);
            } else {
                float bx = bias[col], by = bias[col + 1];
                v0 = acc[mf][nf][0] + bx; v1 = acc[mf][nf][1] + by;
                v2 = acc[mf][nf][2] + bx; v3 = acc[mf][nf][3] + by;
            }
            *(float2*)(C + (size_t)row       * Nc + col) = make_float2(v0, v1);
            *(float2*)(C + (size_t)(row + 8) * Nc + col) = make_float2(v2, v3);
        }
    }
}

__global__ __launch_bounds__(512) void gemm_qk(
    const float* __restrict__ x,
    const float* __restrict__ Wq, const float* __restrict__ Wk,
    float* __restrict__ Qo, float* __restrict__ Ko)
{
    const float* W = (blockIdx.z == 0) ? Wq : Wk;
    float*       C = (blockIdx.z == 0) ? Qo : Ko;
    float scale    = (blockIdx.z == 0) ? 0.125f : 1.0f;
    gemm_body<true>(x, W, C, nullptr, scale, DIMC, HH * DHD);
}

__global__ __launch_bounds__(512) void gemm_v(
    const float* __restrict__ x, const float* __restrict__ Wv,
    float* __restrict__ Vo)
{
    gemm_body<true>(x, Wv, Vo, nullptr, 1.0f, DIMC, HH * DHD);
}

__global__ __launch_bounds__(512) void gemm_out(
    const float* __restrict__ A, const float* __restrict__ W,
    float* __restrict__ C, const float* __restrict__ bias)
{
    gemm_body<false>(A, W, C, bias, 1.0f, DIMC, DIMC);
}

// ---------------------------------------------------------------------------
// qk_sums: per (m-tile, head): loop over all 8 K-chunks with double-buffered
// cp.async. Q tile held as register fragments. Refill of chunk c+2 is issued
// right after the MMAs of chunk c, so the load hides behind exp+store.
// Writes E = exp(S) and per-row inverse sums. No max subtraction.
// ---------------------------------------------------------------------------
#define QKS_SMEM ((128 * 68 + 2 * 128 * 68) * 4)   // 104448 B

__global__ __launch_bounds__(512) void qk_sums(
    const float* __restrict__ Q, const float* __restrict__ Kt,
    float* __restrict__ Sexp, float* __restrict__ inv)
{
    extern __shared__ float smq[];
    float* Qs = smq;                 // [128][68]
    float* Ks = smq + 128 * 68;      // [2][128][68]
    __shared__ float rowpart[128][4];

    const int t     = threadIdx.x;
    const int wid   = t >> 5, lane = t & 31;
    const int group = lane >> 2, tig = lane & 3;
    const int wm    = (wid & 3) * 32;
    const int wn    = (wid >> 2) * 32;
    const int m0    = blockIdx.x * 128;
    const int bh    = blockIdx.y;
    const int b     = bh >> 4, h = bh & 15;
    const size_t base = (size_t)b * NN * DIMC + (size_t)h * DHD;

    auto loadK = [&](int buf, int c) {
        float* Td = Ks + buf * (128 * 68);
        #pragma unroll
        for (int p = 0; p < 4; p++) {
            int l = p * 512 + t;
            int r = l >> 4, d4 = (l & 15) * 4;
            cp16(Td + r * 68 + d4, Kt + base + (size_t)(c * 128 + r) * DIMC + d4);
        }
    };

    // G0: Q tile
    #pragma unroll
    for (int p = 0; p < 4; p++) {
        int l = p * 512 + t;
        int r = l >> 4, d4 = (l & 15) * 4;
        cp16(Qs + r * 68 + d4, Q + base + (size_t)(m0 + r) * DIMC + d4);
    }
    cp_commit();
    loadK(0, 0); cp_commit();    // G1
    loadK(1, 1); cp_commit();    // G2

    cp_wait2();                  // Q resident
    __syncthreads();

    // Q fragments -> registers (reused for all 8 chunks)
    uint32_t qa[2][8][4];
    #pragma unroll
    for (int ks = 0; ks < 8; ks++) {
        int kk = ks * 8;
        #pragma unroll
        for (int mf = 0; mf < 2; mf++) {
            int mb = wm + mf * 16;
            qa[mf][ks][0] = __float_as_uint(Qs[(mb + group    ) * 68 + kk + tig    ]);
            qa[mf][ks][1] = __float_as_uint(Qs[(mb + group + 8) * 68 + kk + tig    ]);
            qa[mf][ks][2] = __float_as_uint(Qs[(mb + group    ) * 68 + kk + tig + 4]);
            qa[mf][ks][3] = __float_as_uint(Qs[(mb + group + 8) * 68 + kk + tig + 4]);
        }
    }

    float sr[4] = {0.f, 0.f, 0.f, 0.f};   // row-sum accumulators

    for (int c = 0; c < 8; c++) {
        cp_wait1();              // K chunk c resident
        __syncthreads();

        const float* Tc = Ks + (c & 1) * (128 * 68);
        float acc[2][4][4] = {};
        #pragma unroll
        for (int ks = 0; ks < 8; ks++) {
            int kk = ks * 8;
            #pragma unroll
            for (int nf = 0; nf < 4; nf++) {
                int nb = wn + nf * 8;
                uint32_t b0 = __float_as_uint(Tc[(nb + group) * 68 + kk + tig    ]);
                uint32_t b1 = __float_as_uint(Tc[(nb + group) * 68 + kk + tig + 4]);
                #pragma unroll
                for (int mf = 0; mf < 2; mf++)
                    MMA_TF32(acc[mf][nf], qa[mf][ks][0], qa[mf][ks][1],
                             qa[mf][ks][2], qa[mf][ks][3], b0, b1);
            }
        }

        // all warps finished reading buffer (c&1): refill NOW so the load
        // overlaps the exp+store phase below
        __syncthreads();
        if (c < 6) loadK(c & 1, c + 2);
        cp_commit();

        // exp + store + accumulate row sums (registers only)
        float* Sb = Sexp + ((size_t)bh * NN + m0) * NN + c * 128;
        #pragma unroll
        for (int mf = 0; mf < 2; mf++) {
            #pragma unroll
            for (int nf = 0; nf < 4; nf++) {
                float e0 = __expf(acc[mf][nf][0]);
                float e1 = __expf(acc[mf][nf][1]);
                float e2 = __expf(acc[mf][nf][2]);
                float e3 = __expf(acc[mf][nf][3]);
                sr[mf * 2    ] += e0 + e1;
                sr[mf * 2 + 1] += e2 + e3;
                int row = wm + mf * 16 + group;
                int col = wn + nf * 8 + tig * 2;
                *(float2*)(Sb + (size_t)row       * NN + col) = make_float2(e0, e1);
                *(float2*)(Sb + (size_t)(row + 8) * NN + col) = make_float2(e2, e3);
            }
        }
    }

    // reduce sums: over tig lanes, then over the 4 n-warp groups
    #pragma unroll
    for (int i = 0; i < 4; i++) {
        sr[i] += __shfl_xor_sync(0xffffffffu, sr[i], 1);
        sr[i] += __shfl_xor_sync(0xffffffffu, sr[i], 2);
    }
    if (tig == 0) {
        #pragma unroll
        for (int mf = 0; mf < 2; mf++) {
            rowpart[wm + mf * 16 + group    ][wid >> 2] = sr[mf * 2    ];
            rowpart[wm + mf * 16 + group + 8][wid >> 2] = sr[mf * 2 + 1];
        }
    }
    __syncthreads();
    if (t < 128) {
        float ssum = rowpart[t][0] + rowpart[t][1] + rowpart[t][2] + rowpart[t][3];
        inv[(size_t)bh * NN + m0 + t] = 1.f / ssum;
    }
}

// ---------------------------------------------------------------------------
// pv_fused: O = (E * inv) @ V ; also writes normalized attn in-place from
// staged smem. 256x64 tile, 512 threads, 16 warps (8m x 2n), 3-stage cp.async.
// ---------------------------------------------------------------------------
#define PV_SMEM ((3 * 256 * 20 + 3 * 16 * 72) * 4)   // 75264 B

__global__ __launch_bounds__(512) void pv_fused(
    float* __restrict__ P, const float* __restrict__ V,
    const float* __restrict__ inv, float* __restrict__ O)
{
    extern __shared__ float smp[];
    float* As = smp;                    // [3][256][20]
    float* Bs = smp + 3 * 5120;         // [3][16][72]

    const int t     = threadIdx.x;
    const int wid   = t >> 5, lane = t & 31;
    const int group = lane >> 2, tig = lane & 3;
    const int wm    = (wid & 7) * 32;
    const int wn    = (wid >> 3) * 32;
    const int m0    = blockIdx.x * 256;
    const int h     = blockIdx.y, b = blockIdx.z;

    const size_t rowbase = ((size_t)b * HH + h) * NN + m0;
    float*       Pb = P + rowbase * NN;
    const float* Vb = V + (size_t)b * NN * DIMC + (size_t)h * DHD;
    float*       Ob = O + (size_t)b * NN * DIMC + (size_t)h * DHD;

    float fi[4];
    #pragma unroll
    for (int mf = 0; mf < 2; mf++) {
        fi[mf * 2    ] = inv[rowbase + wm + mf * 16 + group    ];
        fi[mf * 2 + 1] = inv[rowbase + wm + mf * 16 + group + 8];
    }
    float wi[2];
    #pragma unroll
    for (int l = 0; l < 2; l++) wi[l] = inv[rowbase + ((l * 512 + t) >> 2)];

    auto load_stage = [&](int s, int k0) {
        float* Ad = As + s * 5120;
        float* Bd = Bs + s * 1152;
        #pragma unroll
        for (int l = 0; l < 2; l++) {
            int c = l * 512 + t;
            int r = c >> 2, k4 = (c & 3) * 4;
            cp16(Ad + r * 20 + k4, Pb + (size_t)r * NN + k0 + k4);
        }
        if (t < 256) {
            int kr = t >> 4, n4 = (t & 15) * 4;
            cp16(Bd + kr * 72 + n4, Vb + (size_t)(k0 + kr) * DIMC + n4);
        }
    };

    float acc[2][4][4] = {};

    load_stage(0, 0);  cp_commit();
    load_stage(1, 16); cp_commit();

    int s = 0;
    for (int k0 = 0; k0 < NN; k0 += 16) {
        cp_wait1();
        __syncthreads();
        int s2 = (s >= 1) ? s - 1 : s + 2;
        if (k0 + 32 < NN) load_stage(s2, k0 + 32);
        cp_commit();

        const float* Ac = As + s * 5120;
        const float* Bc = Bs + s * 1152;

        // write normalized attn chunk back to gmem (from staged raw expS)
        #pragma unroll
        for (int l = 0; l < 2; l++) {
            int c = l * 512 + t;
            int r = c >> 2, k4 = (c & 3) * 4;
            const float* src = Ac + r * 20 + k4;
            float4 v;
            v.x = src[0] * wi[l]; v.y = src[1] * wi[l];
            v.z = src[2] * wi[l]; v.w = src[3] * wi[l];
            *(float4*)(Pb + (size_t)r * NN + k0 + k4) = v;
        }

        #pragma unroll
        for (int ks = 0; ks < 2; ks++) {
            int kk = ks * 8;
            uint32_t a[2][4];
            #pragma unroll
            for (int mf = 0; mf < 2; mf++) {
                int mb = wm + mf * 16;
                a[mf][0] = __float_as_uint(tf32r(Ac[(mb + group    ) * 20 + kk + tig    ] * fi[mf * 2    ]));
                a[mf][1] = __float_as_uint(tf32r(Ac[(mb + group + 8) * 20 + kk + tig    ] * fi[mf * 2 + 1]));
                a[mf][2] = __float_as_uint(tf32r(Ac[(mb + group    ) * 20 + kk + tig + 4] * fi[mf * 2    ]));
                a[mf][3] = __float_as_uint(tf32r(Ac[(mb + group + 8) * 20 + kk + tig + 4] * fi[mf * 2 + 1]));
            }
            #pragma unroll
            for (int nf = 0; nf < 4; nf++) {
                int nb = wn + nf * 8;
                uint32_t b0 = __float_as_uint(Bc[(kk + tig    ) * 72 + nb + group]);
                uint32_t b1 = __float_as_uint(Bc[(kk + tig + 4) * 72 + nb + group]);
                #pragma unroll
                for (int mf = 0; mf < 2; mf++)
                    MMA_TF32(acc[mf][nf], a[mf][0], a[mf][1], a[mf][2], a[mf][3], b0, b1);
            }
        }
        s = (s == 2) ? 0 : s + 1;
        __syncthreads();
    }

    #pragma unroll
    for (int mf = 0; mf < 2; mf++) {
        #pragma unroll
        for (int nf = 0; nf < 4; nf++) {
            int row = m0 + wm + mf * 16 + group;
            int col = wn + nf * 8 + tig * 2;
            *(float2*)(Ob + (size_t)row       * DIMC + col) =
                make_float2(tf32r(acc[mf][nf][0]), tf32r(acc[mf][nf][1]));
            *(float2*)(Ob + (size_t)(row + 8) * DIMC + col) =
                make_float2(tf32r(acc[mf][nf][2]), tf32r(acc[mf][nf][3]));
        }
    }
}

// ---------------------------------------------------------------------------
extern "C" void kernel_launch(void* const* d_in, const int* in_sizes, int n_in,
                              void* d_out, int out_size)
{
    const float* x  = (const float*)d_in[0];
    const float* Wq = (const float*)d_in[1];
    const float* Wk = (const float*)d_in[2];
    const float* Wv = (const float*)d_in[3];
    const float* Wo = (const float*)d_in[4];
    const float* bo = (const float*)d_in[5];

    float* out  = (float*)d_out;
    float* attn = out + (size_t)BB * NN * DIMC;

    float *Qp, *Kp, *Vp, *Op, *Xr, *Wqr, *Wkr, *Wvr, *Wor, *Iv;
    cudaGetSymbolAddress((void**)&Qp,  g_Q);
    cudaGetSymbolAddress((void**)&Kp,  g_K);
    cudaGetSymbolAddress((void**)&Vp,  g_V);
    cudaGetSymbolAddress((void**)&Op,  g_O);
    cudaGetSymbolAddress((void**)&Xr,  g_Xr);
    cudaGetSymbolAddress((void**)&Wqr, g_Wqr);
    cudaGetSymbolAddress((void**)&Wkr, g_Wkr);
    cudaGetSymbolAddress((void**)&Wvr, g_Wvr);
    cudaGetSymbolAddress((void**)&Wor, g_Wor);
    cudaGetSymbolAddress((void**)&Iv,  g_inv);

    cudaFuncSetAttribute(gemm_qk,  cudaFuncAttributeMaxDynamicSharedMemorySize, GEMM_SMEM);
    cudaFuncSetAttribute(gemm_v,   cudaFuncAttributeMaxDynamicSharedMemorySize, GEMM_SMEM);
    cudaFuncSetAttribute(gemm_out, cudaFuncAttributeMaxDynamicSharedMemorySize, GEMM_SMEM);
    cudaFuncSetAttribute(qk_sums,  cudaFuncAttributeMaxDynamicSharedMemorySize, QKS_SMEM);
    cudaFuncSetAttribute(pv_fused, cudaFuncAttributeMaxDynamicSharedMemorySize, PV_SMEM);

    // Side stream for the V projection (runs concurrently with qk_sums).
    // Created per call and intentionally not destroyed: destroying a stream
    // that participated in an ongoing graph capture would invalidate it.
    cudaStream_t sv;
    cudaStreamCreateWithFlags(&sv, cudaStreamNonBlocking);
    cudaEvent_t eR, eV;
    cudaEventCreateWithFlags(&eR, cudaEventDisableTiming);
    cudaEventCreateWithFlags(&eV, cudaEventDisableTiming);

    round_all<<<8192, 256>>>(x, Wq, Wk, Wv, Wo, Xr, Wqr, Wkr, Wvr, Wor);
    cudaEventRecord(eR, 0);

    // fork: V projection on side stream
    cudaStreamWaitEvent(sv, eR, 0);
    dim3 gV(8, 32);
    gemm_v<<<gV, 512, GEMM_SMEM, sv>>>(Xr, Wvr, Vp);
    cudaEventRecord(eV, sv);

    // main stream: Q,K projections then score path
    dim3 gQK2(8, 32, 2);
    gemm_qk<<<gQK2, 512, GEMM_SMEM>>>(Xr, Wqr, Wkr, Qp, Kp);

    dim3 gQK(8, BB * HH);    // (m-tiles, b*16+h)
    qk_sums<<<gQK, 512, QKS_SMEM>>>(Qp, Kp, attn, Iv);

    // join: pv needs V
    cudaStreamWaitEvent(0, eV, 0);

    dim3 gPV(NN / 256, HH, BB);
    pv_fused<<<gPV, 512, PV_SMEM>>>(attn, Vp, Iv, Op);

    dim3 gOut(8, 32);
    gemm_out<<<gOut, 512, GEMM_SMEM>>>(Op, Wor, out, bo);
}

// round 12
// speedup vs baseline: 1.4710x; 1.4710x over previous
#include <cuda_runtime.h>
#include <cuda_fp16.h>
#include <cstdint>
#include <cstddef>

#define BB   4
#define NN   1024
#define DIMC 1024
#define HH   16
#define DHD  64

// Scratch (no cudaMalloc allowed)
__device__ __half g_Xh [(size_t)BB * NN * DIMC];
__device__ __half g_WqT[(size_t)DIMC * DIMC];
__device__ __half g_WkT[(size_t)DIMC * DIMC];
__device__ __half g_WvT[(size_t)DIMC * DIMC];
__device__ __half g_WoT[(size_t)DIMC * DIMC];
__device__ __half g_Qh [(size_t)BB * NN * DIMC];
__device__ __half g_Kh [(size_t)BB * NN * DIMC];
__device__ __half g_Vh [(size_t)BB * NN * DIMC];
__device__ __half g_Vt [(size_t)BB * DIMC * NN];   // [b*1024 + d][j]
__device__ __half g_Oh [(size_t)BB * NN * DIMC];
__device__ float  g_inv[(size_t)BB * HH * NN];     // 1/rowsum

__device__ __forceinline__ void cp16(void* smem, const void* gmem) {
    uint32_t s = (uint32_t)__cvta_generic_to_shared(smem);
    asm volatile("cp.async.cg.shared.global [%0], [%1], 16;" :: "r"(s), "l"(gmem));
}
__device__ __forceinline__ void cp_commit() { asm volatile("cp.async.commit_group;"); }
__device__ __forceinline__ void cp_wait1()  { asm volatile("cp.async.wait_group 1;"); }
__device__ __forceinline__ void cp_wait2()  { asm volatile("cp.async.wait_group 2;"); }

#define MMA_F16(d, a0, a1, a2, a3, b0, b1)                                  \
    asm volatile(                                                           \
        "mma.sync.aligned.m16n8k16.row.col.f32.f16.f16.f32 "                \
        "{%0,%1,%2,%3}, {%4,%5,%6,%7}, {%8,%9}, {%0,%1,%2,%3};"             \
        : "+f"(d[0]), "+f"(d[1]), "+f"(d[2]), "+f"(d[3])                    \
        : "r"(a0), "r"(a1), "r"(a2), "r"(a3), "r"(b0), "r"(b1))

__device__ __forceinline__ uint32_t h2u(__half2 h) {
    return *reinterpret_cast<uint32_t*>(&h);
}

// ---------------------------------------------------------------------------
// round_xh: Xh = half(x), 4M elements.
// ---------------------------------------------------------------------------
__global__ __launch_bounds__(256) void round_xh(
    const float* __restrict__ x, __half* __restrict__ xh)
{
    int i = blockIdx.x * 256 + threadIdx.x;     // float4 index, 1M total
    float4 v = ((const float4*)x)[i];
    __half2 h0 = __floats2half2_rn(v.x, v.y);
    __half2 h1 = __floats2half2_rn(v.z, v.w);
    uint2 u; u.x = h2u(h0); u.y = h2u(h1);
    ((uint2*)xh)[i] = u;
}

// ---------------------------------------------------------------------------
// wtransh: Wt[n][k] = half(W[k][n]) for all four weights.
// ---------------------------------------------------------------------------
__global__ __launch_bounds__(256) void wtransh(
    const float* __restrict__ Wq, const float* __restrict__ Wk,
    const float* __restrict__ Wv, const float* __restrict__ Wo,
    __half* __restrict__ qt, __half* __restrict__ kt,
    __half* __restrict__ vt, __half* __restrict__ ot)
{
    __shared__ float tile[32][33];
    int z = blockIdx.z;
    const float* W = (z == 0) ? Wq : (z == 1) ? Wk : (z == 2) ? Wv : Wo;
    __half*      T = (z == 0) ? qt : (z == 1) ? kt : (z == 2) ? vt : ot;
    int bx = blockIdx.x * 32, by = blockIdx.y * 32;
    int tx = threadIdx.x & 31, ty = threadIdx.x >> 5;
    #pragma unroll
    for (int r = 0; r < 32; r += 8)
        tile[ty + r][tx] = W[(size_t)(by + ty + r) * DIMC + bx + tx];
    __syncthreads();
    #pragma unroll
    for (int r = 0; r < 32; r += 8)
        T[(size_t)(bx + ty + r) * DIMC + by + tx] = __float2half_rn(tile[tx][ty + r]);
}

// ---------------------------------------------------------------------------
// vtrans: Vt[b*1024 + d][j] = Vh[b][j][d].
// ---------------------------------------------------------------------------
__global__ __launch_bounds__(256) void vtrans(
    const __half* __restrict__ Vh, __half* __restrict__ Vt)
{
    __shared__ __half tile[32][33];
    int j0 = blockIdx.x * 32, d0 = blockIdx.y * 32, b = blockIdx.z;
    int tx = threadIdx.x & 31, ty = threadIdx.x >> 5;
    #pragma unroll
    for (int r = 0; r < 32; r += 8)
        tile[ty + r][tx] = Vh[((size_t)b * NN + j0 + ty + r) * DIMC + d0 + tx];
    __syncthreads();
    #pragma unroll
    for (int r = 0; r < 32; r += 8)
        Vt[((size_t)b * DIMC + d0 + ty + r) * NN + j0 + tx] = tile[tx][ty + r];
}

// ---------------------------------------------------------------------------
// fp16 GEMM: C = A[M,K] @ Bt[N,K]^T. 128x128 tile, BK=32 halfs, 512 threads
// (16 warps, 4m x 4n, warp tile 32x32), 3-stage cp.async. Strides 40 halfs
// (80B -> bank c=20, conflict-free fragment reads).
// ---------------------------------------------------------------------------
#define HG_SMEM (3 * 2 * 5120 * 2)   // 61440 B

template<bool HALF_OUT>
__device__ __forceinline__ void hgemm_body(
    const __half* __restrict__ A, const __half* __restrict__ Bt,
    void* __restrict__ Cout, const float* __restrict__ bias,
    float outScale, int K, int Nc)
{
    extern __shared__ __half smh[];
    __half* As = smh;             // [3][128][40]
    __half* Bs = smh + 3 * 5120;  // [3][128][40]

    const int t     = threadIdx.x;
    const int wid   = t >> 5, lane = t & 31;
    const int group = lane >> 2, tig = lane & 3;
    const int wm    = (wid & 3) * 32;
    const int wn    = (wid >> 2) * 32;
    const int m0    = blockIdx.y * 128;
    const int n0    = blockIdx.x * 128;

    auto load_stage = [&](int s, int k0) {
        __half* Ad = As + s * 5120;
        __half* Bd = Bs + s * 5120;
        int r = t >> 2, c8 = (t & 3) * 8;
        cp16(Ad + r * 40 + c8, A  + (size_t)(m0 + r) * K + k0 + c8);
        cp16(Bd + r * 40 + c8, Bt + (size_t)(n0 + r) * K + k0 + c8);
    };

    float acc[2][4][4] = {};
    load_stage(0, 0);  cp_commit();
    load_stage(1, 32); cp_commit();

    int s = 0;
    for (int k0 = 0; k0 < K; k0 += 32) {
        cp_wait1();
        __syncthreads();
        int s2 = (s >= 1) ? s - 1 : s + 2;
        if (k0 + 64 < K) load_stage(s2, k0 + 64);
        cp_commit();

        const __half* Ac = As + s * 5120;
        const __half* Bc = Bs + s * 5120;
        #pragma unroll
        for (int ks = 0; ks < 2; ks++) {
            int ko = ks * 16;
            uint32_t a[2][4];
            #pragma unroll
            for (int mf = 0; mf < 2; mf++) {
                const __half* Ar = Ac + (wm + mf * 16 + group) * 40 + 2 * tig + ko;
                a[mf][0] = *(const uint32_t*)(Ar);
                a[mf][1] = *(const uint32_t*)(Ar + 320);   // row +8
                a[mf][2] = *(const uint32_t*)(Ar + 8);     // k +8
                a[mf][3] = *(const uint32_t*)(Ar + 328);
            }
            #pragma unroll
            for (int nf = 0; nf < 4; nf++) {
                const __half* Br = Bc + (wn + nf * 8 + group) * 40 + 2 * tig + ko;
                uint32_t b0 = *(const uint32_t*)(Br);
                uint32_t b1 = *(const uint32_t*)(Br + 8);
                #pragma unroll
                for (int mf = 0; mf < 2; mf++)
                    MMA_F16(acc[mf][nf], a[mf][0], a[mf][1], a[mf][2], a[mf][3], b0, b1);
            }
        }
        s = (s == 2) ? 0 : s + 1;
        __syncthreads();
    }

    #pragma unroll
    for (int mf = 0; mf < 2; mf++) {
        #pragma unroll
        for (int nf = 0; nf < 4; nf++) {
            int row = m0 + wm + mf * 16 + group;
            int col = n0 + wn + nf * 8 + tig * 2;
            if (HALF_OUT) {
                __half* C = (__half*)Cout;
                *(__half2*)(C + (size_t)row       * Nc + col) =
                    __floats2half2_rn(acc[mf][nf][0] * outScale, acc[mf][nf][1] * outScale);
                *(__half2*)(C + (size_t)(row + 8) * Nc + col) =
                    __floats2half2_rn(acc[mf][nf][2] * outScale, acc[mf][nf][3] * outScale);
            } else {
                float* C = (float*)Cout;
                float bx = bias[col], by = bias[col + 1];
                *(float2*)(C + (size_t)row       * Nc + col) =
                    make_float2(acc[mf][nf][0] + bx, acc[mf][nf][1] + by);
                *(float2*)(C + (size_t)(row + 8) * Nc + col) =
                    make_float2(acc[mf][nf][2] + bx, acc[mf][nf][3] + by);
            }
        }
    }
}

__global__ __launch_bounds__(512) void hgemm_qkv(
    const __half* __restrict__ x,
    const __half* __restrict__ WqT, const __half* __restrict__ WkT,
    const __half* __restrict__ WvT,
    __half* __restrict__ Qo, __half* __restrict__ Ko, __half* __restrict__ Vo)
{
    const __half* W = (blockIdx.z == 0) ? WqT : (blockIdx.z == 1) ? WkT : WvT;
    __half*       C = (blockIdx.z == 0) ? Qo : (blockIdx.z == 1) ? Ko : Vo;
    float scale     = (blockIdx.z == 0) ? 0.125f : 1.0f;
    hgemm_body<true>(x, W, C, nullptr, scale, DIMC, HH * DHD);
}

__global__ __launch_bounds__(512) void hgemm_out(
    const __half* __restrict__ A, const __half* __restrict__ WoT,
    float* __restrict__ C, const float* __restrict__ bias)
{
    hgemm_body<false>(A, WoT, C, bias, 1.0f, DIMC, DIMC);
}

// ---------------------------------------------------------------------------
// qk_sums: per (m-tile 128, head): S = Qs @ K^T via f16 MMA; E = exp(S)
// stored fp32 + 1/rowsum. Double-buffered cp.async K chunks; Q fragments in
// registers. Tile stride 88 halfs (176B -> bank c=12, conflict-free).
// ---------------------------------------------------------------------------
#define QKS_SMEM (3 * 128 * 88 * 2)   // 67584 B

__global__ __launch_bounds__(512) void qk_sums(
    const __half* __restrict__ Q, const __half* __restrict__ Kt,
    float* __restrict__ Sexp, float* __restrict__ inv)
{
    extern __shared__ __half smq[];
    __half* Qs = smq;                 // [128][88]
    __half* Ks = smq + 128 * 88;      // [2][128][88]
    __shared__ float rowpart[128][4];

    const int t     = threadIdx.x;
    const int wid   = t >> 5, lane = t & 31;
    const int group = lane >> 2, tig = lane & 3;
    const int wm    = (wid & 3) * 32;
    const int wn    = (wid >> 2) * 32;
    const int m0    = blockIdx.x * 128;
    const int bh    = blockIdx.y;
    const int b     = bh >> 4, h = bh & 15;
    const size_t base = (size_t)b * NN * DIMC + (size_t)h * DHD;

    auto loadK = [&](int buf, int c) {
        __half* Td = Ks + buf * (128 * 88);
        #pragma unroll
        for (int p = 0; p < 2; p++) {
            int i = p * 512 + t;
            int r = i >> 3, c8 = (i & 7) * 8;
            cp16(Td + r * 88 + c8, Kt + base + (size_t)(c * 128 + r) * DIMC + c8);
        }
    };

    #pragma unroll
    for (int p = 0; p < 2; p++) {
        int i = p * 512 + t;
        int r = i >> 3, c8 = (i & 7) * 8;
        cp16(Qs + r * 88 + c8, Q + base + (size_t)(m0 + r) * DIMC + c8);
    }
    cp_commit();
    loadK(0, 0); cp_commit();
    loadK(1, 1); cp_commit();

    cp_wait2();
    __syncthreads();

    uint32_t qa[2][4][4];
    #pragma unroll
    for (int ks = 0; ks < 4; ks++) {
        int ko = ks * 16;
        #pragma unroll
        for (int mf = 0; mf < 2; mf++) {
            const __half* Ar = Qs + (wm + mf * 16 + group) * 88 + 2 * tig + ko;
            qa[mf][ks][0] = *(const uint32_t*)(Ar);
            qa[mf][ks][1] = *(const uint32_t*)(Ar + 704);   // row +8
            qa[mf][ks][2] = *(const uint32_t*)(Ar + 8);
            qa[mf][ks][3] = *(const uint32_t*)(Ar + 712);
        }
    }

    float sr[4] = {0.f, 0.f, 0.f, 0.f};

    for (int c = 0; c < 8; c++) {
        cp_wait1();
        __syncthreads();

        const __half* Tc = Ks + (c & 1) * (128 * 88);
        float acc[2][4][4] = {};
        #pragma unroll
        for (int ks = 0; ks < 4; ks++) {
            int ko = ks * 16;
            #pragma unroll
            for (int nf = 0; nf < 4; nf++) {
                const __half* Br = Tc + (wn + nf * 8 + group) * 88 + 2 * tig + ko;
                uint32_t b0 = *(const uint32_t*)(Br);
                uint32_t b1 = *(const uint32_t*)(Br + 8);
                #pragma unroll
                for (int mf = 0; mf < 2; mf++)
                    MMA_F16(acc[mf][nf], qa[mf][ks][0], qa[mf][ks][1],
                            qa[mf][ks][2], qa[mf][ks][3], b0, b1);
            }
        }

        __syncthreads();
        if (c < 6) loadK(c & 1, c + 2);
        cp_commit();

        float* Sb = Sexp + ((size_t)bh * NN + m0) * NN + c * 128;
        #pragma unroll
        for (int mf = 0; mf < 2; mf++) {
            #pragma unroll
            for (int nf = 0; nf < 4; nf++) {
                float e0 = __expf(acc[mf][nf][0]);
                float e1 = __expf(acc[mf][nf][1]);
                float e2 = __expf(acc[mf][nf][2]);
                float e3 = __expf(acc[mf][nf][3]);
                sr[mf * 2    ] += e0 + e1;
                sr[mf * 2 + 1] += e2 + e3;
                int row = wm + mf * 16 + group;
                int col = wn + nf * 8 + tig * 2;
                *(float2*)(Sb + (size_t)row       * NN + col) = make_float2(e0, e1);
                *(float2*)(Sb + (size_t)(row + 8) * NN + col) = make_float2(e2, e3);
            }
        }
    }

    #pragma unroll
    for (int i = 0; i < 4; i++) {
        sr[i] += __shfl_xor_sync(0xffffffffu, sr[i], 1);
        sr[i] += __shfl_xor_sync(0xffffffffu, sr[i], 2);
    }
    if (tig == 0) {
        #pragma unroll
        for (int mf = 0; mf < 2; mf++) {
            rowpart[wm + mf * 16 + group    ][wid >> 2] = sr[mf * 2    ];
            rowpart[wm + mf * 16 + group + 8][wid >> 2] = sr[mf * 2 + 1];
        }
    }
    __syncthreads();
    if (t < 128) {
        float ssum = rowpart[t][0] + rowpart[t][1] + rowpart[t][2] + rowpart[t][3];
        inv[(size_t)bh * NN + m0 + t] = 1.f / ssum;
    }
}

// ---------------------------------------------------------------------------
// pv_fused: O = (E * inv) @ V via f16 MMA; writes normalized attn in-place
// from staged fp32 smem; O emitted as half (feeds hgemm_out). 256x64 tile,
// 512 threads (8m x 2n warps, 32x32 each), BK=16, 3-stage cp.async.
// V operand from Vt[d][j] (stride 24 halfs = 48B -> bank c=12, clean).
// ---------------------------------------------------------------------------
#define PV_SMEM (3 * 256 * 20 * 4 + 3 * 64 * 24 * 2)   // 70656 B

__global__ __launch_bounds__(512) void pv_fused(
    float* __restrict__ P, const __half* __restrict__ Vt,
    const float* __restrict__ inv, __half* __restrict__ Oh)
{
    extern __shared__ float smp[];
    float*  As = smp;                           // [3][256][20]
    __half* Bs = (__half*)(smp + 3 * 5120);     // [3][64][24]

    const int t     = threadIdx.x;
    const int wid   = t >> 5, lane = t & 31;
    const int group = lane >> 2, tig = lane & 3;
    const int wm    = (wid & 7) * 32;
    const int wn    = (wid >> 3) * 32;
    const int m0    = blockIdx.x * 256;
    const int h     = blockIdx.y, b = blockIdx.z;

    const size_t rowbase = ((size_t)b * HH + h) * NN + m0;
    float*        Pb  = P + rowbase * NN;
    const __half* Vtb = Vt + ((size_t)b * DIMC + h * DHD) * NN;
    __half*       Ob  = Oh + (size_t)b * NN * DIMC + (size_t)h * DHD;

    float fi[4];
    #pragma unroll
    for (int mf = 0; mf < 2; mf++) {
        fi[mf * 2    ] = inv[rowbase + wm + mf * 16 + group    ];
        fi[mf * 2 + 1] = inv[rowbase + wm + mf * 16 + group + 8];
    }
    float wi[2];
    #pragma unroll
    for (int l = 0; l < 2; l++) wi[l] = inv[rowbase + ((l * 512 + t) >> 2)];

    auto load_stage = [&](int s, int k0) {
        float*  Ad = As + s * 5120;
        __half* Bd = Bs + s * 1536;
        #pragma unroll
        for (int l = 0; l < 2; l++) {
            int c = l * 512 + t;
            int r = c >> 2, k4 = (c & 3) * 4;
            cp16(Ad + r * 20 + k4, Pb + (size_t)r * NN + k0 + k4);
        }
        if (t < 128) {
            int r = t >> 1, c8 = (t & 1) * 8;
            cp16(Bd + r * 24 + c8, Vtb + (size_t)r * NN + k0 + c8);
        }
    };

    float acc[2][4][4] = {};

    load_stage(0, 0);  cp_commit();
    load_stage(1, 16); cp_commit();

    int s = 0;
    for (int k0 = 0; k0 < NN; k0 += 16) {
        cp_wait1();
        __syncthreads();
        int s2 = (s >= 1) ? s - 1 : s + 2;
        if (k0 + 32 < NN) load_stage(s2, k0 + 32);
        cp_commit();

        const float*  Ac = As + s * 5120;
        const __half* Bc = Bs + s * 1536;

        // normalized attn write-back from staged raw expS
        #pragma unroll
        for (int l = 0; l < 2; l++) {
            int c = l * 512 + t;
            int r = c >> 2, k4 = (c & 3) * 4;
            const float* src = Ac + r * 20 + k4;
            float4 v;
            v.x = src[0] * wi[l]; v.y = src[1] * wi[l];
            v.z = src[2] * wi[l]; v.w = src[3] * wi[l];
            *(float4*)(Pb + (size_t)r * NN + k0 + k4) = v;
        }

        uint32_t a[2][4];
        #pragma unroll
        for (int mf = 0; mf < 2; mf++) {
            const float* Ar0 = Ac + (wm + mf * 16 + group) * 20 + 2 * tig;
            const float* Ar1 = Ar0 + 160;   // row +8
            float f0 = fi[mf * 2], f1 = fi[mf * 2 + 1];
            a[mf][0] = h2u(__floats2half2_rn(Ar0[0] * f0, Ar0[1] * f0));
            a[mf][1] = h2u(__floats2half2_rn(Ar1[0] * f1, Ar1[1] * f1));
            a[mf][2] = h2u(__floats2half2_rn(Ar0[8] * f0, Ar0[9] * f0));
            a[mf][3] = h2u(__floats2half2_rn(Ar1[8] * f1, Ar1[9] * f1));
        }
        #pragma unroll
        for (int nf = 0; nf < 4; nf++) {
            const __half* Br = Bc + (wn + nf * 8 + group) * 24 + 2 * tig;
            uint32_t b0 = *(const uint32_t*)(Br);
            uint32_t b1 = *(const uint32_t*)(Br + 8);
            #pragma unroll
            for (int mf = 0; mf < 2; mf++)
                MMA_F16(acc[mf][nf], a[mf][0], a[mf][1], a[mf][2], a[mf][3], b0, b1);
        }
        s = (s == 2) ? 0 : s + 1;
        __syncthreads();
    }

    #pragma unroll
    for (int mf = 0; mf < 2; mf++) {
        #pragma unroll
        for (int nf = 0; nf < 4; nf++) {
            int row = m0 + wm + mf * 16 + group;
            int col = wn + nf * 8 + tig * 2;
            *(__half2*)(Ob + (size_t)row       * DIMC + col) =
                __floats2half2_rn(acc[mf][nf][0], acc[mf][nf][1]);
            *(__half2*)(Ob + (size_t)(row + 8) * DIMC + col) =
                __floats2half2_rn(acc[mf][nf][2], acc[mf][nf][3]);
        }
    }
}

// ---------------------------------------------------------------------------
extern "C" void kernel_launch(void* const* d_in, const int* in_sizes, int n_in,
                              void* d_out, int out_size)
{
    const float* x  = (const float*)d_in[0];
    const float* Wq = (const float*)d_in[1];
    const float* Wk = (const float*)d_in[2];
    const float* Wv = (const float*)d_in[3];
    const float* Wo = (const float*)d_in[4];
    const float* bo = (const float*)d_in[5];

    float* out  = (float*)d_out;
    float* attn = out + (size_t)BB * NN * DIMC;

    __half *Xh, *WqT, *WkT, *WvT, *WoT, *Qh, *Kh, *Vh, *Vt, *Oh;
    float* Iv;
    cudaGetSymbolAddress((void**)&Xh,  g_Xh);
    cudaGetSymbolAddress((void**)&WqT, g_WqT);
    cudaGetSymbolAddress((void**)&WkT, g_WkT);
    cudaGetSymbolAddress((void**)&WvT, g_WvT);
    cudaGetSymbolAddress((void**)&WoT, g_WoT);
    cudaGetSymbolAddress((void**)&Qh,  g_Qh);
    cudaGetSymbolAddress((void**)&Kh,  g_Kh);
    cudaGetSymbolAddress((void**)&Vh,  g_Vh);
    cudaGetSymbolAddress((void**)&Vt,  g_Vt);
    cudaGetSymbolAddress((void**)&Oh,  g_Oh);
    cudaGetSymbolAddress((void**)&Iv,  g_inv);

    cudaFuncSetAttribute(hgemm_qkv, cudaFuncAttributeMaxDynamicSharedMemorySize, HG_SMEM);
    cudaFuncSetAttribute(hgemm_out, cudaFuncAttributeMaxDynamicSharedMemorySize, HG_SMEM);
    cudaFuncSetAttribute(qk_sums,   cudaFuncAttributeMaxDynamicSharedMemorySize, QKS_SMEM);
    cudaFuncSetAttribute(pv_fused,  cudaFuncAttributeMaxDynamicSharedMemorySize, PV_SMEM);

    round_xh<<<4096, 256>>>(x, Xh);

    dim3 gT(32, 32, 4);
    wtransh<<<gT, 256>>>(Wq, Wk, Wv, Wo, WqT, WkT, WvT, WoT);

    dim3 gQKV(8, 32, 3);
    hgemm_qkv<<<gQKV, 512, HG_SMEM>>>(Xh, WqT, WkT, WvT, Qh, Kh, Vh);

    dim3 gVT(32, 32, BB);
    vtrans<<<gVT, 256>>>(Vh, Vt);

    dim3 gQK(8, BB * HH);
    qk_sums<<<gQK, 512, QKS_SMEM>>>(Qh, Kh, attn, Iv);

    dim3 gPV(NN / 256, HH, BB);
    pv_fused<<<gPV, 512, PV_SMEM>>>(attn, Vt, Iv, Oh);

    dim3 gOut(8, 32);
    hgemm_out<<<gOut, 512, HG_SMEM>>>(Oh, WoT, out, bo);
}

// round 13
// speedup vs baseline: 1.4935x; 1.0153x over previous
#include <cuda_runtime.h>
#include <cuda_fp16.h>
#include <cstdint>
#include <cstddef>

#define BB   4
#define NN   1024
#define DIMC 1024
#define HH   16
#define DHD  64

// Scratch (no cudaMalloc allowed)
__device__ __half g_Xh [(size_t)BB * NN * DIMC];
__device__ __half g_WqT[(size_t)DIMC * DIMC];
__device__ __half g_WkT[(size_t)DIMC * DIMC];
__device__ __half g_WvT[(size_t)DIMC * DIMC];
__device__ __half g_WoT[(size_t)DIMC * DIMC];
__device__ __half g_Qh [(size_t)BB * NN * DIMC];
__device__ __half g_Kh [(size_t)BB * NN * DIMC];
__device__ __half g_Vt [(size_t)BB * DIMC * NN];   // [b*1024 + d][j]
__device__ __half g_Oh [(size_t)BB * NN * DIMC];
__device__ float  g_inv[(size_t)BB * HH * NN];     // 1/rowsum

__device__ __forceinline__ void cp16(void* smem, const void* gmem) {
    uint32_t s = (uint32_t)__cvta_generic_to_shared(smem);
    asm volatile("cp.async.cg.shared.global [%0], [%1], 16;" :: "r"(s), "l"(gmem));
}
__device__ __forceinline__ void cp_commit() { asm volatile("cp.async.commit_group;"); }
__device__ __forceinline__ void cp_wait1()  { asm volatile("cp.async.wait_group 1;"); }
__device__ __forceinline__ void cp_wait2()  { asm volatile("cp.async.wait_group 2;"); }

#define MMA_F16(d, a0, a1, a2, a3, b0, b1)                                  \
    asm volatile(                                                           \
        "mma.sync.aligned.m16n8k16.row.col.f32.f16.f16.f32 "                \
        "{%0,%1,%2,%3}, {%4,%5,%6,%7}, {%8,%9}, {%0,%1,%2,%3};"             \
        : "+f"(d[0]), "+f"(d[1]), "+f"(d[2]), "+f"(d[3])                    \
        : "r"(a0), "r"(a1), "r"(a2), "r"(a3), "r"(b0), "r"(b1))

__device__ __forceinline__ uint32_t h2u(__half2 h) {
    return *reinterpret_cast<uint32_t*>(&h);
}

// ---------------------------------------------------------------------------
// prep: z=0: Xh = half(x) (1024 blocks handle 1M float4);
//       z=1..4: Wt[n][k] = half(W[k][n]).
// ---------------------------------------------------------------------------
__global__ __launch_bounds__(256) void prep(
    const float* __restrict__ x,
    const float* __restrict__ Wq, const float* __restrict__ Wk,
    const float* __restrict__ Wv, const float* __restrict__ Wo,
    __half* __restrict__ xh,
    __half* __restrict__ qt, __half* __restrict__ kt,
    __half* __restrict__ vt, __half* __restrict__ ot)
{
    int z = blockIdx.z;
    if (z == 0) {
        int bid = blockIdx.y * 32 + blockIdx.x;
        #pragma unroll
        for (int k = 0; k < 4; k++) {
            int i = bid * 1024 + k * 256 + threadIdx.x;
            float4 v = ((const float4*)x)[i];
            uint2 u;
            u.x = h2u(__floats2half2_rn(v.x, v.y));
            u.y = h2u(__floats2half2_rn(v.z, v.w));
            ((uint2*)xh)[i] = u;
        }
        return;
    }
    __shared__ float tile[32][33];
    const float* W = (z == 1) ? Wq : (z == 2) ? Wk : (z == 3) ? Wv : Wo;
    __half*      T = (z == 1) ? qt : (z == 2) ? kt : (z == 3) ? vt : ot;
    int bx = blockIdx.x * 32, by = blockIdx.y * 32;
    int tx = threadIdx.x & 31, ty = threadIdx.x >> 5;
    #pragma unroll
    for (int r = 0; r < 32; r += 8)
        tile[ty + r][tx] = W[(size_t)(by + ty + r) * DIMC + bx + tx];
    __syncthreads();
    #pragma unroll
    for (int r = 0; r < 32; r += 8)
        T[(size_t)(bx + ty + r) * DIMC + by + tx] = __float2half_rn(tile[tx][ty + r]);
}

// ---------------------------------------------------------------------------
// fp16 GEMM: C = A[M,K] @ Bt[N,K]^T. 128x128 tile, BK=32 halfs, 512 threads
// (16 warps, 4m x 4n, warp tile 32x32), 3-stage cp.async.
// MODE 0: half out, scaled. MODE 1: float out + bias. MODE 2: write Vt
// transposed (Vt[b*1024+d][j] = half(acc)), via smem transpose stage.
// ---------------------------------------------------------------------------
#define HG_SMEM (3 * 2 * 5120 * 2)   // 61440 B

template<int MODE>
__device__ __forceinline__ void hgemm_body(
    const __half* __restrict__ A, const __half* __restrict__ Bt,
    void* __restrict__ Cout, const float* __restrict__ bias,
    __half* __restrict__ Vt, float outScale, int K, int Nc)
{
    extern __shared__ __half smh[];
    __half* As = smh;             // [3][128][40]
    __half* Bs = smh + 3 * 5120;  // [3][128][40]

    const int t     = threadIdx.x;
    const int wid   = t >> 5, lane = t & 31;
    const int group = lane >> 2, tig = lane & 3;
    const int wm    = (wid & 3) * 32;
    const int wn    = (wid >> 2) * 32;
    const int m0    = blockIdx.y * 128;
    const int n0    = blockIdx.x * 128;

    auto load_stage = [&](int s, int k0) {
        __half* Ad = As + s * 5120;
        __half* Bd = Bs + s * 5120;
        int r = t >> 2, c8 = (t & 3) * 8;
        cp16(Ad + r * 40 + c8, A  + (size_t)(m0 + r) * K + k0 + c8);
        cp16(Bd + r * 40 + c8, Bt + (size_t)(n0 + r) * K + k0 + c8);
    };

    float acc[2][4][4] = {};
    load_stage(0, 0);  cp_commit();
    load_stage(1, 32); cp_commit();

    int s = 0;
    for (int k0 = 0; k0 < K; k0 += 32) {
        cp_wait1();
        __syncthreads();
        int s2 = (s >= 1) ? s - 1 : s + 2;
        if (k0 + 64 < K) load_stage(s2, k0 + 64);
        cp_commit();

        const __half* Ac = As + s * 5120;
        const __half* Bc = Bs + s * 5120;
        #pragma unroll
        for (int ks = 0; ks < 2; ks++) {
            int ko = ks * 16;
            uint32_t a[2][4];
            #pragma unroll
            for (int mf = 0; mf < 2; mf++) {
                const __half* Ar = Ac + (wm + mf * 16 + group) * 40 + 2 * tig + ko;
                a[mf][0] = *(const uint32_t*)(Ar);
                a[mf][1] = *(const uint32_t*)(Ar + 320);
                a[mf][2] = *(const uint32_t*)(Ar + 8);
                a[mf][3] = *(const uint32_t*)(Ar + 328);
            }
            #pragma unroll
            for (int nf = 0; nf < 4; nf++) {
                const __half* Br = Bc + (wn + nf * 8 + group) * 40 + 2 * tig + ko;
                uint32_t b0 = *(const uint32_t*)(Br);
                uint32_t b1 = *(const uint32_t*)(Br + 8);
                #pragma unroll
                for (int mf = 0; mf < 2; mf++)
                    MMA_F16(acc[mf][nf], a[mf][0], a[mf][1], a[mf][2], a[mf][3], b0, b1);
            }
        }
        s = (s == 2) ? 0 : s + 1;
        __syncthreads();
    }

    if (MODE == 2) {
        // Transpose through smem: st[col][row], then coalesced Vt rows.
        __half* st = smh;   // 128 x 132 halfs = 33792 B (fits in 61440)
        #pragma unroll
        for (int mf = 0; mf < 2; mf++) {
            #pragma unroll
            for (int nf = 0; nf < 4; nf++) {
                int row = wm + mf * 16 + group;
                int col = wn + nf * 8 + tig * 2;
                st[(col    ) * 132 + row    ] = __float2half_rn(acc[mf][nf][0]);
                st[(col + 1) * 132 + row    ] = __float2half_rn(acc[mf][nf][1]);
                st[(col    ) * 132 + row + 8] = __float2half_rn(acc[mf][nf][2]);
                st[(col + 1) * 132 + row + 8] = __float2half_rn(acc[mf][nf][3]);
            }
        }
        __syncthreads();
        int b  = m0 >> 10;
        int j0 = m0 & 1023;
        #pragma unroll
        for (int p = 0; p < 16; p++) {
            int i = p * 512 + t;       // 8192 u32 positions
            int d = i >> 6, c2 = (i & 63) * 2;
            uint32_t v = *(const uint32_t*)(st + d * 132 + c2);
            *(uint32_t*)(Vt + ((size_t)b * DIMC + n0 + d) * NN + j0 + c2) = v;
        }
        return;
    }

    #pragma unroll
    for (int mf = 0; mf < 2; mf++) {
        #pragma unroll
        for (int nf = 0; nf < 4; nf++) {
            int row = m0 + wm + mf * 16 + group;
            int col = n0 + wn + nf * 8 + tig * 2;
            if (MODE == 0) {
                __half* C = (__half*)Cout;
                *(__half2*)(C + (size_t)row       * Nc + col) =
                    __floats2half2_rn(acc[mf][nf][0] * outScale, acc[mf][nf][1] * outScale);
                *(__half2*)(C + (size_t)(row + 8) * Nc + col) =
                    __floats2half2_rn(acc[mf][nf][2] * outScale, acc[mf][nf][3] * outScale);
            } else {
                float* C = (float*)Cout;
                float bx = bias[col], by = bias[col + 1];
                *(float2*)(C + (size_t)row       * Nc + col) =
                    make_float2(acc[mf][nf][0] + bx, acc[mf][nf][1] + by);
                *(float2*)(C + (size_t)(row + 8) * Nc + col) =
                    make_float2(acc[mf][nf][2] + bx, acc[mf][nf][3] + by);
            }
        }
    }
}

__global__ __launch_bounds__(512) void hgemm_qkv(
    const __half* __restrict__ x,
    const __half* __restrict__ WqT, const __half* __restrict__ WkT,
    const __half* __restrict__ WvT,
    __half* __restrict__ Qo, __half* __restrict__ Ko, __half* __restrict__ Vt)
{
    if (blockIdx.z == 0)
        hgemm_body<0>(x, WqT, Qo, nullptr, nullptr, 0.125f, DIMC, HH * DHD);
    else if (blockIdx.z == 1)
        hgemm_body<0>(x, WkT, Ko, nullptr, nullptr, 1.0f, DIMC, HH * DHD);
    else
        hgemm_body<2>(x, WvT, nullptr, nullptr, Vt, 1.0f, DIMC, HH * DHD);
}

__global__ __launch_bounds__(512) void hgemm_out(
    const __half* __restrict__ A, const __half* __restrict__ WoT,
    float* __restrict__ C, const float* __restrict__ bias)
{
    hgemm_body<1>(A, WoT, C, bias, nullptr, 1.0f, DIMC, DIMC);
}

// ---------------------------------------------------------------------------
// qk_sums: per (m-tile 128, head): S = Qs @ K^T via f16 MMA; E = exp(S)
// stored fp32 + 1/rowsum. Double-buffered cp.async K chunks.
// ---------------------------------------------------------------------------
#define QKS_SMEM (3 * 128 * 88 * 2)   // 67584 B

__global__ __launch_bounds__(512) void qk_sums(
    const __half* __restrict__ Q, const __half* __restrict__ Kt,
    float* __restrict__ Sexp, float* __restrict__ inv)
{
    extern __shared__ __half smq[];
    __half* Qs = smq;                 // [128][88]
    __half* Ks = smq + 128 * 88;      // [2][128][88]
    __shared__ float rowpart[128][4];

    const int t     = threadIdx.x;
    const int wid   = t >> 5, lane = t & 31;
    const int group = lane >> 2, tig = lane & 3;
    const int wm    = (wid & 3) * 32;
    const int wn    = (wid >> 2) * 32;
    const int m0    = blockIdx.x * 128;
    const int bh    = blockIdx.y;
    const int b     = bh >> 4, h = bh & 15;
    const size_t base = (size_t)b * NN * DIMC + (size_t)h * DHD;

    auto loadK = [&](int buf, int c) {
        __half* Td = Ks + buf * (128 * 88);
        #pragma unroll
        for (int p = 0; p < 2; p++) {
            int i = p * 512 + t;
            int r = i >> 3, c8 = (i & 7) * 8;
            cp16(Td + r * 88 + c8, Kt + base + (size_t)(c * 128 + r) * DIMC + c8);
        }
    };

    #pragma unroll
    for (int p = 0; p < 2; p++) {
        int i = p * 512 + t;
        int r = i >> 3, c8 = (i & 7) * 8;
        cp16(Qs + r * 88 + c8, Q + base + (size_t)(m0 + r) * DIMC + c8);
    }
    cp_commit();
    loadK(0, 0); cp_commit();
    loadK(1, 1); cp_commit();

    cp_wait2();
    __syncthreads();

    uint32_t qa[2][4][4];
    #pragma unroll
    for (int ks = 0; ks < 4; ks++) {
        int ko = ks * 16;
        #pragma unroll
        for (int mf = 0; mf < 2; mf++) {
            const __half* Ar = Qs + (wm + mf * 16 + group) * 88 + 2 * tig + ko;
            qa[mf][ks][0] = *(const uint32_t*)(Ar);
            qa[mf][ks][1] = *(const uint32_t*)(Ar + 704);
            qa[mf][ks][2] = *(const uint32_t*)(Ar + 8);
            qa[mf][ks][3] = *(const uint32_t*)(Ar + 712);
        }
    }

    float sr[4] = {0.f, 0.f, 0.f, 0.f};

    for (int c = 0; c < 8; c++) {
        cp_wait1();
        __syncthreads();

        const __half* Tc = Ks + (c & 1) * (128 * 88);
        float acc[2][4][4] = {};
        #pragma unroll
        for (int ks = 0; ks < 4; ks++) {
            int ko = ks * 16;
            #pragma unroll
            for (int nf = 0; nf < 4; nf++) {
                const __half* Br = Tc + (wn + nf * 8 + group) * 88 + 2 * tig + ko;
                uint32_t b0 = *(const uint32_t*)(Br);
                uint32_t b1 = *(const uint32_t*)(Br + 8);
                #pragma unroll
                for (int mf = 0; mf < 2; mf++)
                    MMA_F16(acc[mf][nf], qa[mf][ks][0], qa[mf][ks][1],
                            qa[mf][ks][2], qa[mf][ks][3], b0, b1);
            }
        }

        __syncthreads();
        if (c < 6) loadK(c & 1, c + 2);
        cp_commit();

        float* Sb = Sexp + ((size_t)bh * NN + m0) * NN + c * 128;
        #pragma unroll
        for (int mf = 0; mf < 2; mf++) {
            #pragma unroll
            for (int nf = 0; nf < 4; nf++) {
                float e0 = __expf(acc[mf][nf][0]);
                float e1 = __expf(acc[mf][nf][1]);
                float e2 = __expf(acc[mf][nf][2]);
                float e3 = __expf(acc[mf][nf][3]);
                sr[mf * 2    ] += e0 + e1;
                sr[mf * 2 + 1] += e2 + e3;
                int row = wm + mf * 16 + group;
                int col = wn + nf * 8 + tig * 2;
                *(float2*)(Sb + (size_t)row       * NN + col) = make_float2(e0, e1);
                *(float2*)(Sb + (size_t)(row + 8) * NN + col) = make_float2(e2, e3);
            }
        }
    }

    #pragma unroll
    for (int i = 0; i < 4; i++) {
        sr[i] += __shfl_xor_sync(0xffffffffu, sr[i], 1);
        sr[i] += __shfl_xor_sync(0xffffffffu, sr[i], 2);
    }
    if (tig == 0) {
        #pragma unroll
        for (int mf = 0; mf < 2; mf++) {
            rowpart[wm + mf * 16 + group    ][wid >> 2] = sr[mf * 2    ];
            rowpart[wm + mf * 16 + group + 8][wid >> 2] = sr[mf * 2 + 1];
        }
    }
    __syncthreads();
    if (t < 128) {
        float ssum = rowpart[t][0] + rowpart[t][1] + rowpart[t][2] + rowpart[t][3];
        inv[(size_t)bh * NN + m0 + t] = 1.f / ssum;
    }
}

// ---------------------------------------------------------------------------
// pv_fused: O = (E * inv) @ V; writes normalized attn in-place. 128x64 tile,
// 256 threads (8 warps: 4m x 2n, 32x32 each), BK=16, 3-stage cp.async.
// Small CTA -> 3 CTAs/SM for latency hiding.
// ---------------------------------------------------------------------------
#define PV_SMEM (3 * 128 * 20 * 4 + 3 * 64 * 24 * 2)   // 39936 B

__global__ __launch_bounds__(256) void pv_fused(
    float* __restrict__ P, const __half* __restrict__ Vt,
    const float* __restrict__ inv, __half* __restrict__ Oh)
{
    extern __shared__ float smp[];
    float*  As = smp;                           // [3][128][20]
    __half* Bs = (__half*)(smp + 3 * 2560);     // [3][64][24]

    const int t     = threadIdx.x;
    const int wid   = t >> 5, lane = t & 31;
    const int group = lane >> 2, tig = lane & 3;
    const int wm    = (wid & 3) * 32;
    const int wn    = (wid >> 2) * 32;
    const int m0    = blockIdx.x * 128;
    const int h     = blockIdx.y, b = blockIdx.z;

    const size_t rowbase = ((size_t)b * HH + h) * NN + m0;
    float*        Pb  = P + rowbase * NN;
    const __half* Vtb = Vt + ((size_t)b * DIMC + h * DHD) * NN;
    __half*       Ob  = Oh + (size_t)b * NN * DIMC + (size_t)h * DHD;

    float fi[4];
    #pragma unroll
    for (int mf = 0; mf < 2; mf++) {
        fi[mf * 2    ] = inv[rowbase + wm + mf * 16 + group    ];
        fi[mf * 2 + 1] = inv[rowbase + wm + mf * 16 + group + 8];
    }
    float wi[2];
    #pragma unroll
    for (int l = 0; l < 2; l++) wi[l] = inv[rowbase + ((l * 256 + t) >> 2)];

    auto load_stage = [&](int s, int k0) {
        float*  Ad = As + s * 2560;
        __half* Bd = Bs + s * 1536;
        #pragma unroll
        for (int l = 0; l < 2; l++) {
            int c = l * 256 + t;
            int r = c >> 2, k4 = (c & 3) * 4;
            cp16(Ad + r * 20 + k4, Pb + (size_t)r * NN + k0 + k4);
        }
        if (t < 128) {
            int r = t >> 1, c8 = (t & 1) * 8;
            cp16(Bd + r * 24 + c8, Vtb + (size_t)r * NN + k0 + c8);
        }
    };

    float acc[2][4][4] = {};

    load_stage(0, 0);  cp_commit();
    load_stage(1, 16); cp_commit();

    int s = 0;
    for (int k0 = 0; k0 < NN; k0 += 16) {
        cp_wait1();
        __syncthreads();
        int s2 = (s >= 1) ? s - 1 : s + 2;
        if (k0 + 32 < NN) load_stage(s2, k0 + 32);
        cp_commit();

        const float*  Ac = As + s * 2560;
        const __half* Bc = Bs + s * 1536;

        // normalized attn write-back from staged raw expS
        #pragma unroll
        for (int l = 0; l < 2; l++) {
            int c = l * 256 + t;
            int r = c >> 2, k4 = (c & 3) * 4;
            const float* src = Ac + r * 20 + k4;
            float4 v;
            v.x = src[0] * wi[l]; v.y = src[1] * wi[l];
            v.z = src[2] * wi[l]; v.w = src[3] * wi[l];
            *(float4*)(Pb + (size_t)r * NN + k0 + k4) = v;
        }

        uint32_t a[2][4];
        #pragma unroll
        for (int mf = 0; mf < 2; mf++) {
            const float* Ar0 = Ac + (wm + mf * 16 + group) * 20 + 2 * tig;
            const float* Ar1 = Ar0 + 160;   // row +8
            float f0 = fi[mf * 2], f1 = fi[mf * 2 + 1];
            a[mf][0] = h2u(__floats2half2_rn(Ar0[0] * f0, Ar0[1] * f0));
            a[mf][1] = h2u(__floats2half2_rn(Ar1[0] * f1, Ar1[1] * f1));
            a[mf][2] = h2u(__floats2half2_rn(Ar0[8] * f0, Ar0[9] * f0));
            a[mf][3] = h2u(__floats2half2_rn(Ar1[8] * f1, Ar1[9] * f1));
        }
        #pragma unroll
        for (int nf = 0; nf < 4; nf++) {
            const __half* Br = Bc + (wn + nf * 8 + group) * 24 + 2 * tig;
            uint32_t b0 = *(const uint32_t*)(Br);
            uint32_t b1 = *(const uint32_t*)(Br + 8);
            #pragma unroll
            for (int mf = 0; mf < 2; mf++)
                MMA_F16(acc[mf][nf], a[mf][0], a[mf][1], a[mf][2], a[mf][3], b0, b1);
        }
        s = (s == 2) ? 0 : s + 1;
        __syncthreads();
    }

    #pragma unroll
    for (int mf = 0; mf < 2; mf++) {
        #pragma unroll
        for (int nf = 0; nf < 4; nf++) {
            int row = m0 + wm + mf * 16 + group;
            int col = wn + nf * 8 + tig * 2;
            *(__half2*)(Ob + (size_t)row       * DIMC + col) =
                __floats2half2_rn(acc[mf][nf][0], acc[mf][nf][1]);
            *(__half2*)(Ob + (size_t)(row + 8) * DIMC + col) =
                __floats2half2_rn(acc[mf][nf][2], acc[mf][nf][3]);
        }
    }
}

// ---------------------------------------------------------------------------
extern "C" void kernel_launch(void* const* d_in, const int* in_sizes, int n_in,
                              void* d_out, int out_size)
{
    const float* x  = (const float*)d_in[0];
    const float* Wq = (const float*)d_in[1];
    const float* Wk = (const float*)d_in[2];
    const float* Wv = (const float*)d_in[3];
    const float* Wo = (const float*)d_in[4];
    const float* bo = (const float*)d_in[5];

    float* out  = (float*)d_out;
    float* attn = out + (size_t)BB * NN * DIMC;

    __half *Xh, *WqT, *WkT, *WvT, *WoT, *Qh, *Kh, *Vt, *Oh;
    float* Iv;
    cudaGetSymbolAddress((void**)&Xh,  g_Xh);
    cudaGetSymbolAddress((void**)&WqT, g_WqT);
    cudaGetSymbolAddress((void**)&WkT, g_WkT);
    cudaGetSymbolAddress((void**)&WvT, g_WvT);
    cudaGetSymbolAddress((void**)&WoT, g_WoT);
    cudaGetSymbolAddress((void**)&Qh,  g_Qh);
    cudaGetSymbolAddress((void**)&Kh,  g_Kh);
    cudaGetSymbolAddress((void**)&Vt,  g_Vt);
    cudaGetSymbolAddress((void**)&Oh,  g_Oh);
    cudaGetSymbolAddress((void**)&Iv,  g_inv);

    cudaFuncSetAttribute(hgemm_qkv, cudaFuncAttributeMaxDynamicSharedMemorySize, HG_SMEM);
    cudaFuncSetAttribute(hgemm_out, cudaFuncAttributeMaxDynamicSharedMemorySize, HG_SMEM);
    cudaFuncSetAttribute(qk_sums,   cudaFuncAttributeMaxDynamicSharedMemorySize, QKS_SMEM);
    cudaFuncSetAttribute(pv_fused,  cudaFuncAttributeMaxDynamicSharedMemorySize, PV_SMEM);

    dim3 gPrep(32, 32, 5);
    prep<<<gPrep, 256>>>(x, Wq, Wk, Wv, Wo, Xh, WqT, WkT, WvT, WoT);

    dim3 gQKV(8, 32, 3);
    hgemm_qkv<<<gQKV, 512, HG_SMEM>>>(Xh, WqT, WkT, WvT, Qh, Kh, Vt);

    dim3 gQK(8, BB * HH);
    qk_sums<<<gQK, 512, QKS_SMEM>>>(Qh, Kh, attn, Iv);

    dim3 gPV(NN / 128, HH, BB);
    pv_fused<<<gPV, 256, PV_SMEM>>>(attn, Vt, Iv, Oh);

    dim3 gOut(8, 32);
    hgemm_out<<<gOut, 512, HG_SMEM>>>(Oh, WoT, out, bo);
}

// round 14
// speedup vs baseline: 1.6634x; 1.1138x over previous
#include <cuda_runtime.h>
#include <cuda_fp16.h>
#include <cstdint>
#include <cstddef>

#define BB   4
#define NN   1024
#define DIMC 1024
#define HH   16
#define DHD  64

// Scratch (no cudaMalloc allowed)
__device__ __half g_Xh [(size_t)BB * NN * DIMC];
__device__ __half g_WqT[(size_t)DIMC * DIMC];
__device__ __half g_WkT[(size_t)DIMC * DIMC];
__device__ __half g_WvT[(size_t)DIMC * DIMC];
__device__ __half g_WoT[(size_t)DIMC * DIMC];
__device__ __half g_Qh [(size_t)BB * NN * DIMC];
__device__ __half g_Kh [(size_t)BB * NN * DIMC];
__device__ __half g_Vt [(size_t)BB * DIMC * NN];   // [b*1024 + d][j]
__device__ __half g_Oh [(size_t)BB * NN * DIMC];
__device__ __half g_Eh [(size_t)BB * HH * NN * NN]; // unnormalized exp(S), fp16
__device__ float  g_inv[(size_t)BB * HH * NN];     // 1/rowsum

__device__ __forceinline__ void cp16(void* smem, const void* gmem) {
    uint32_t s = (uint32_t)__cvta_generic_to_shared(smem);
    asm volatile("cp.async.cg.shared.global [%0], [%1], 16;" :: "r"(s), "l"(gmem));
}
__device__ __forceinline__ void cp_commit() { asm volatile("cp.async.commit_group;"); }
__device__ __forceinline__ void cp_wait1()  { asm volatile("cp.async.wait_group 1;"); }
__device__ __forceinline__ void cp_wait2()  { asm volatile("cp.async.wait_group 2;"); }

#define MMA_F16(d, a0, a1, a2, a3, b0, b1)                                  \
    asm volatile(                                                           \
        "mma.sync.aligned.m16n8k16.row.col.f32.f16.f16.f32 "                \
        "{%0,%1,%2,%3}, {%4,%5,%6,%7}, {%8,%9}, {%0,%1,%2,%3};"             \
        : "+f"(d[0]), "+f"(d[1]), "+f"(d[2]), "+f"(d[3])                    \
        : "r"(a0), "r"(a1), "r"(a2), "r"(a3), "r"(b0), "r"(b1))

__device__ __forceinline__ uint32_t h2u(__half2 h) {
    return *reinterpret_cast<uint32_t*>(&h);
}

// Scale a packed half2 by an fp32 factor with fp32 intermediate precision.
__device__ __forceinline__ uint32_t scale_h2(uint32_t u, float f) {
    __half2 h = *reinterpret_cast<__half2*>(&u);
    float2 fv = __half22float2(h);
    return h2u(__floats2half2_rn(fv.x * f, fv.y * f));
}

// ---------------------------------------------------------------------------
// prep: z=0: Xh = half(x); z=1..4: Wt[n][k] = half(W[k][n]).
// ---------------------------------------------------------------------------
__global__ __launch_bounds__(256) void prep(
    const float* __restrict__ x,
    const float* __restrict__ Wq, const float* __restrict__ Wk,
    const float* __restrict__ Wv, const float* __restrict__ Wo,
    __half* __restrict__ xh,
    __half* __restrict__ qt, __half* __restrict__ kt,
    __half* __restrict__ vt, __half* __restrict__ ot)
{
    int z = blockIdx.z;
    if (z == 0) {
        int bid = blockIdx.y * 32 + blockIdx.x;
        #pragma unroll
        for (int k = 0; k < 4; k++) {
            int i = bid * 1024 + k * 256 + threadIdx.x;
            float4 v = ((const float4*)x)[i];
            uint2 u;
            u.x = h2u(__floats2half2_rn(v.x, v.y));
            u.y = h2u(__floats2half2_rn(v.z, v.w));
            ((uint2*)xh)[i] = u;
        }
        return;
    }
    __shared__ float tile[32][33];
    const float* W = (z == 1) ? Wq : (z == 2) ? Wk : (z == 3) ? Wv : Wo;
    __half*      T = (z == 1) ? qt : (z == 2) ? kt : (z == 3) ? vt : ot;
    int bx = blockIdx.x * 32, by = blockIdx.y * 32;
    int tx = threadIdx.x & 31, ty = threadIdx.x >> 5;
    #pragma unroll
    for (int r = 0; r < 32; r += 8)
        tile[ty + r][tx] = W[(size_t)(by + ty + r) * DIMC + bx + tx];
    __syncthreads();
    #pragma unroll
    for (int r = 0; r < 32; r += 8)
        T[(size_t)(bx + ty + r) * DIMC + by + tx] = __float2half_rn(tile[tx][ty + r]);
}

// ---------------------------------------------------------------------------
// fp16 GEMM: C = A[M,K] @ Bt[N,K]^T. 128x128 tile, BK=32 halfs, 512 threads
// (16 warps, 4m x 4n, warp tile 32x32), 3-stage cp.async.
// MODE 0: half out, scaled. MODE 1: float out + bias. MODE 2: write Vt
// transposed via smem stage.
// ---------------------------------------------------------------------------
#define HG_SMEM (3 * 2 * 5120 * 2)   // 61440 B

template<int MODE>
__device__ __forceinline__ void hgemm_body(
    const __half* __restrict__ A, const __half* __restrict__ Bt,
    void* __restrict__ Cout, const float* __restrict__ bias,
    __half* __restrict__ Vt, float outScale, int K, int Nc)
{
    extern __shared__ __half smh[];
    __half* As = smh;             // [3][128][40]
    __half* Bs = smh + 3 * 5120;  // [3][128][40]

    const int t     = threadIdx.x;
    const int wid   = t >> 5, lane = t & 31;
    const int group = lane >> 2, tig = lane & 3;
    const int wm    = (wid & 3) * 32;
    const int wn    = (wid >> 2) * 32;
    const int m0    = blockIdx.y * 128;
    const int n0    = blockIdx.x * 128;

    auto load_stage = [&](int s, int k0) {
        __half* Ad = As + s * 5120;
        __half* Bd = Bs + s * 5120;
        int r = t >> 2, c8 = (t & 3) * 8;
        cp16(Ad + r * 40 + c8, A  + (size_t)(m0 + r) * K + k0 + c8);
        cp16(Bd + r * 40 + c8, Bt + (size_t)(n0 + r) * K + k0 + c8);
    };

    float acc[2][4][4] = {};
    load_stage(0, 0);  cp_commit();
    load_stage(1, 32); cp_commit();

    int s = 0;
    for (int k0 = 0; k0 < K; k0 += 32) {
        cp_wait1();
        __syncthreads();
        int s2 = (s >= 1) ? s - 1 : s + 2;
        if (k0 + 64 < K) load_stage(s2, k0 + 64);
        cp_commit();

        const __half* Ac = As + s * 5120;
        const __half* Bc = Bs + s * 5120;
        #pragma unroll
        for (int ks = 0; ks < 2; ks++) {
            int ko = ks * 16;
            uint32_t a[2][4];
            #pragma unroll
            for (int mf = 0; mf < 2; mf++) {
                const __half* Ar = Ac + (wm + mf * 16 + group) * 40 + 2 * tig + ko;
                a[mf][0] = *(const uint32_t*)(Ar);
                a[mf][1] = *(const uint32_t*)(Ar + 320);
                a[mf][2] = *(const uint32_t*)(Ar + 8);
                a[mf][3] = *(const uint32_t*)(Ar + 328);
            }
            #pragma unroll
            for (int nf = 0; nf < 4; nf++) {
                const __half* Br = Bc + (wn + nf * 8 + group) * 40 + 2 * tig + ko;
                uint32_t b0 = *(const uint32_t*)(Br);
                uint32_t b1 = *(const uint32_t*)(Br + 8);
                #pragma unroll
                for (int mf = 0; mf < 2; mf++)
                    MMA_F16(acc[mf][nf], a[mf][0], a[mf][1], a[mf][2], a[mf][3], b0, b1);
            }
        }
        s = (s == 2) ? 0 : s + 1;
        __syncthreads();
    }

    if (MODE == 2) {
        __half* st = smh;   // 128 x 132 halfs
        #pragma unroll
        for (int mf = 0; mf < 2; mf++) {
            #pragma unroll
            for (int nf = 0; nf < 4; nf++) {
                int row = wm + mf * 16 + group;
                int col = wn + nf * 8 + tig * 2;
                st[(col    ) * 132 + row    ] = __float2half_rn(acc[mf][nf][0]);
                st[(col + 1) * 132 + row    ] = __float2half_rn(acc[mf][nf][1]);
                st[(col    ) * 132 + row + 8] = __float2half_rn(acc[mf][nf][2]);
                st[(col + 1) * 132 + row + 8] = __float2half_rn(acc[mf][nf][3]);
            }
        }
        __syncthreads();
        int b  = m0 >> 10;
        int j0 = m0 & 1023;
        #pragma unroll
        for (int p = 0; p < 16; p++) {
            int i = p * 512 + t;
            int d = i >> 6, c2 = (i & 63) * 2;
            uint32_t v = *(const uint32_t*)(st + d * 132 + c2);
            *(uint32_t*)(Vt + ((size_t)b * DIMC + n0 + d) * NN + j0 + c2) = v;
        }
        return;
    }

    #pragma unroll
    for (int mf = 0; mf < 2; mf++) {
        #pragma unroll
        for (int nf = 0; nf < 4; nf++) {
            int row = m0 + wm + mf * 16 + group;
            int col = n0 + wn + nf * 8 + tig * 2;
            if (MODE == 0) {
                __half* C = (__half*)Cout;
                *(__half2*)(C + (size_t)row       * Nc + col) =
                    __floats2half2_rn(acc[mf][nf][0] * outScale, acc[mf][nf][1] * outScale);
                *(__half2*)(C + (size_t)(row + 8) * Nc + col) =
                    __floats2half2_rn(acc[mf][nf][2] * outScale, acc[mf][nf][3] * outScale);
            } else {
                float* C = (float*)Cout;
                float bx = bias[col], by = bias[col + 1];
                *(float2*)(C + (size_t)row       * Nc + col) =
                    make_float2(acc[mf][nf][0] + bx, acc[mf][nf][1] + by);
                *(float2*)(C + (size_t)(row + 8) * Nc + col) =
                    make_float2(acc[mf][nf][2] + bx, acc[mf][nf][3] + by);
            }
        }
    }
}

__global__ __launch_bounds__(512) void hgemm_qkv(
    const __half* __restrict__ x,
    const __half* __restrict__ WqT, const __half* __restrict__ WkT,
    const __half* __restrict__ WvT,
    __half* __restrict__ Qo, __half* __restrict__ Ko, __half* __restrict__ Vt)
{
    if (blockIdx.z == 0)
        hgemm_body<0>(x, WqT, Qo, nullptr, nullptr, 0.125f, DIMC, HH * DHD);
    else if (blockIdx.z == 1)
        hgemm_body<0>(x, WkT, Ko, nullptr, nullptr, 1.0f, DIMC, HH * DHD);
    else
        hgemm_body<2>(x, WvT, nullptr, nullptr, Vt, 1.0f, DIMC, HH * DHD);
}

__global__ __launch_bounds__(512) void hgemm_out(
    const __half* __restrict__ A, const __half* __restrict__ WoT,
    float* __restrict__ C, const float* __restrict__ bias)
{
    hgemm_body<1>(A, WoT, C, bias, nullptr, 1.0f, DIMC, DIMC);
}

// ---------------------------------------------------------------------------
// qk_sums: per (m-tile 128, head): S = Qs @ K^T via f16 MMA; stores
// E = exp(S) as fp16 (unnormalized) + 1/rowsum. Double-buffered cp.async.
// ---------------------------------------------------------------------------
#define QKS_SMEM (3 * 128 * 88 * 2)   // 67584 B

__global__ __launch_bounds__(512) void qk_sums(
    const __half* __restrict__ Q, const __half* __restrict__ Kt,
    __half* __restrict__ Eh, float* __restrict__ inv)
{
    extern __shared__ __half smq[];
    __half* Qs = smq;                 // [128][88]
    __half* Ks = smq + 128 * 88;      // [2][128][88]
    __shared__ float rowpart[128][4];

    const int t     = threadIdx.x;
    const int wid   = t >> 5, lane = t & 31;
    const int group = lane >> 2, tig = lane & 3;
    const int wm    = (wid & 3) * 32;
    const int wn    = (wid >> 2) * 32;
    const int m0    = blockIdx.x * 128;
    const int bh    = blockIdx.y;
    const int b     = bh >> 4, h = bh & 15;
    const size_t base = (size_t)b * NN * DIMC + (size_t)h * DHD;

    auto loadK = [&](int buf, int c) {
        __half* Td = Ks + buf * (128 * 88);
        #pragma unroll
        for (int p = 0; p < 2; p++) {
            int i = p * 512 + t;
            int r = i >> 3, c8 = (i & 7) * 8;
            cp16(Td + r * 88 + c8, Kt + base + (size_t)(c * 128 + r) * DIMC + c8);
        }
    };

    #pragma unroll
    for (int p = 0; p < 2; p++) {
        int i = p * 512 + t;
        int r = i >> 3, c8 = (i & 7) * 8;
        cp16(Qs + r * 88 + c8, Q + base + (size_t)(m0 + r) * DIMC + c8);
    }
    cp_commit();
    loadK(0, 0); cp_commit();
    loadK(1, 1); cp_commit();

    cp_wait2();
    __syncthreads();

    uint32_t qa[2][4][4];
    #pragma unroll
    for (int ks = 0; ks < 4; ks++) {
        int ko = ks * 16;
        #pragma unroll
        for (int mf = 0; mf < 2; mf++) {
            const __half* Ar = Qs + (wm + mf * 16 + group) * 88 + 2 * tig + ko;
            qa[mf][ks][0] = *(const uint32_t*)(Ar);
            qa[mf][ks][1] = *(const uint32_t*)(Ar + 704);
            qa[mf][ks][2] = *(const uint32_t*)(Ar + 8);
            qa[mf][ks][3] = *(const uint32_t*)(Ar + 712);
        }
    }

    float sr[4] = {0.f, 0.f, 0.f, 0.f};

    for (int c = 0; c < 8; c++) {
        cp_wait1();
        __syncthreads();

        const __half* Tc = Ks + (c & 1) * (128 * 88);
        float acc[2][4][4] = {};
        #pragma unroll
        for (int ks = 0; ks < 4; ks++) {
            int ko = ks * 16;
            #pragma unroll
            for (int nf = 0; nf < 4; nf++) {
                const __half* Br = Tc + (wn + nf * 8 + group) * 88 + 2 * tig + ko;
                uint32_t b0 = *(const uint32_t*)(Br);
                uint32_t b1 = *(const uint32_t*)(Br + 8);
                #pragma unroll
                for (int mf = 0; mf < 2; mf++)
                    MMA_F16(acc[mf][nf], qa[mf][ks][0], qa[mf][ks][1],
                            qa[mf][ks][2], qa[mf][ks][3], b0, b1);
            }
        }

        __syncthreads();
        if (c < 6) loadK(c & 1, c + 2);
        cp_commit();

        __half* Sb = Eh + ((size_t)bh * NN + m0) * NN + c * 128;
        #pragma unroll
        for (int mf = 0; mf < 2; mf++) {
            #pragma unroll
            for (int nf = 0; nf < 4; nf++) {
                float e0 = __expf(acc[mf][nf][0]);
                float e1 = __expf(acc[mf][nf][1]);
                float e2 = __expf(acc[mf][nf][2]);
                float e3 = __expf(acc[mf][nf][3]);
                sr[mf * 2    ] += e0 + e1;
                sr[mf * 2 + 1] += e2 + e3;
                int row = wm + mf * 16 + group;
                int col = wn + nf * 8 + tig * 2;
                *(__half2*)(Sb + (size_t)row       * NN + col) = __floats2half2_rn(e0, e1);
                *(__half2*)(Sb + (size_t)(row + 8) * NN + col) = __floats2half2_rn(e2, e3);
            }
        }
    }

    #pragma unroll
    for (int i = 0; i < 4; i++) {
        sr[i] += __shfl_xor_sync(0xffffffffu, sr[i], 1);
        sr[i] += __shfl_xor_sync(0xffffffffu, sr[i], 2);
    }
    if (tig == 0) {
        #pragma unroll
        for (int mf = 0; mf < 2; mf++) {
            rowpart[wm + mf * 16 + group    ][wid >> 2] = sr[mf * 2    ];
            rowpart[wm + mf * 16 + group + 8][wid >> 2] = sr[mf * 2 + 1];
        }
    }
    __syncthreads();
    if (t < 128) {
        float ssum = rowpart[t][0] + rowpart[t][1] + rowpart[t][2] + rowpart[t][3];
        inv[(size_t)bh * NN + m0 + t] = 1.f / ssum;
    }
}

// ---------------------------------------------------------------------------
// pv_fused: O = (E * inv) @ V ; writes normalized attn (fp32) from staged
// fp16 E. 128x64 tile, 256 threads (8 warps: 4m x 2n), BK=16, 3-stage
// cp.async. E smem stride 24 halfs -> conflict-free u32 fragment loads.
// ---------------------------------------------------------------------------
#define PV_SMEM ((3 * 128 * 24 + 3 * 64 * 24) * 2)   // 27648 B

__global__ __launch_bounds__(256) void pv_fused(
    const __half* __restrict__ Eh, float* __restrict__ attn,
    const __half* __restrict__ Vt,
    const float* __restrict__ inv, __half* __restrict__ Oh)
{
    extern __shared__ __half smv[];
    __half* As = smv;                  // [3][128][24]
    __half* Bs = smv + 3 * 128 * 24;   // [3][64][24]

    const int t     = threadIdx.x;
    const int wid   = t >> 5, lane = t & 31;
    const int group = lane >> 2, tig = lane & 3;
    const int wm    = (wid & 3) * 32;
    const int wn    = (wid >> 2) * 32;
    const int m0    = blockIdx.x * 128;
    const int h     = blockIdx.y, b = blockIdx.z;

    const size_t rowbase = ((size_t)b * HH + h) * NN + m0;
    const __half* Eb  = Eh + rowbase * NN;
    float*        Pb  = attn + rowbase * NN;
    const __half* Vtb = Vt + ((size_t)b * DIMC + h * DHD) * NN;
    __half*       Ob  = Oh + (size_t)b * NN * DIMC + (size_t)h * DHD;

    float fi[4];
    #pragma unroll
    for (int mf = 0; mf < 2; mf++) {
        fi[mf * 2    ] = inv[rowbase + wm + mf * 16 + group    ];
        fi[mf * 2 + 1] = inv[rowbase + wm + mf * 16 + group + 8];
    }
    float wi[2];
    #pragma unroll
    for (int l = 0; l < 2; l++) wi[l] = inv[rowbase + ((l * 256 + t) >> 2)];

    auto load_stage = [&](int s, int k0) {
        __half* Ad = As + s * (128 * 24);
        __half* Bd = Bs + s * (64 * 24);
        {
            int r = t >> 1, c8 = (t & 1) * 8;
            cp16(Ad + r * 24 + c8, Eb + (size_t)r * NN + k0 + c8);
        }
        if (t < 128) {
            int r = t >> 1, c8 = (t & 1) * 8;
            cp16(Bd + r * 24 + c8, Vtb + (size_t)r * NN + k0 + c8);
        }
    };

    float acc[2][4][4] = {};

    load_stage(0, 0);  cp_commit();
    load_stage(1, 16); cp_commit();

    int s = 0;
    for (int k0 = 0; k0 < NN; k0 += 16) {
        cp_wait1();
        __syncthreads();
        int s2 = (s >= 1) ? s - 1 : s + 2;
        if (k0 + 32 < NN) load_stage(s2, k0 + 32);
        cp_commit();

        const __half* Ac = As + s * (128 * 24);
        const __half* Bc = Bs + s * (64 * 24);

        // normalized attn write (fp32) from staged fp16 E
        #pragma unroll
        for (int l = 0; l < 2; l++) {
            int c = l * 256 + t;
            int r = c >> 2, k4 = (c & 3) * 4;
            const __half* src = Ac + r * 24 + k4;
            __half2 h0 = *(const __half2*)(src);
            __half2 h1 = *(const __half2*)(src + 2);
            float wl = wi[l];
            float4 v;
            v.x = __low2float(h0) * wl; v.y = __high2float(h0) * wl;
            v.z = __low2float(h1) * wl; v.w = __high2float(h1) * wl;
            *(float4*)(Pb + (size_t)r * NN + k0 + k4) = v;
        }

        uint32_t a[2][4];
        #pragma unroll
        for (int mf = 0; mf < 2; mf++) {
            const __half* Ar = Ac + (wm + mf * 16 + group) * 24 + 2 * tig;
            float f0 = fi[mf * 2], f1 = fi[mf * 2 + 1];
            a[mf][0] = scale_h2(*(const uint32_t*)(Ar      ), f0);
            a[mf][1] = scale_h2(*(const uint32_t*)(Ar + 192), f1);   // row +8
            a[mf][2] = scale_h2(*(const uint32_t*)(Ar +   8), f0);   // k +8
            a[mf][3] = scale_h2(*(const uint32_t*)(Ar + 200), f1);
        }
        #pragma unroll
        for (int nf = 0; nf < 4; nf++) {
            const __half* Br = Bc + (wn + nf * 8 + group) * 24 + 2 * tig;
            uint32_t b0 = *(const uint32_t*)(Br);
            uint32_t b1 = *(const uint32_t*)(Br + 8);
            #pragma unroll
            for (int mf = 0; mf < 2; mf++)
                MMA_F16(acc[mf][nf], a[mf][0], a[mf][1], a[mf][2], a[mf][3], b0, b1);
        }
        s = (s == 2) ? 0 : s + 1;
        __syncthreads();
    }

    #pragma unroll
    for (int mf = 0; mf < 2; mf++) {
        #pragma unroll
        for (int nf = 0; nf < 4; nf++) {
            int row = m0 + wm + mf * 16 + group;
            int col = wn + nf * 8 + tig * 2;
            *(__half2*)(Ob + (size_t)row       * DIMC + col) =
                __floats2half2_rn(acc[mf][nf][0], acc[mf][nf][1]);
            *(__half2*)(Ob + (size_t)(row + 8) * DIMC + col) =
                __floats2half2_rn(acc[mf][nf][2], acc[mf][nf][3]);
        }
    }
}

// ---------------------------------------------------------------------------
extern "C" void kernel_launch(void* const* d_in, const int* in_sizes, int n_in,
                              void* d_out, int out_size)
{
    const float* x  = (const float*)d_in[0];
    const float* Wq = (const float*)d_in[1];
    const float* Wk = (const float*)d_in[2];
    const float* Wv = (const float*)d_in[3];
    const float* Wo = (const float*)d_in[4];
    const float* bo = (const float*)d_in[5];

    float* out  = (float*)d_out;
    float* attn = out + (size_t)BB * NN * DIMC;

    __half *Xh, *WqT, *WkT, *WvT, *WoT, *Qh, *Kh, *Vt, *Oh, *Eh;
    float* Iv;
    cudaGetSymbolAddress((void**)&Xh,  g_Xh);
    cudaGetSymbolAddress((void**)&WqT, g_WqT);
    cudaGetSymbolAddress((void**)&WkT, g_WkT);
    cudaGetSymbolAddress((void**)&WvT, g_WvT);
    cudaGetSymbolAddress((void**)&WoT, g_WoT);
    cudaGetSymbolAddress((void**)&Qh,  g_Qh);
    cudaGetSymbolAddress((void**)&Kh,  g_Kh);
    cudaGetSymbolAddress((void**)&Vt,  g_Vt);
    cudaGetSymbolAddress((void**)&Oh,  g_Oh);
    cudaGetSymbolAddress((void**)&Eh,  g_Eh);
    cudaGetSymbolAddress((void**)&Iv,  g_inv);

    cudaFuncSetAttribute(hgemm_qkv, cudaFuncAttributeMaxDynamicSharedMemorySize, HG_SMEM);
    cudaFuncSetAttribute(hgemm_out, cudaFuncAttributeMaxDynamicSharedMemorySize, HG_SMEM);
    cudaFuncSetAttribute(qk_sums,   cudaFuncAttributeMaxDynamicSharedMemorySize, QKS_SMEM);
    cudaFuncSetAttribute(pv_fused,  cudaFuncAttributeMaxDynamicSharedMemorySize, PV_SMEM);

    dim3 gPrep(32, 32, 5);
    prep<<<gPrep, 256>>>(x, Wq, Wk, Wv, Wo, Xh, WqT, WkT, WvT, WoT);

    dim3 gQKV(8, 32, 3);
    hgemm_qkv<<<gQKV, 512, HG_SMEM>>>(Xh, WqT, WkT, WvT, Qh, Kh, Vt);

    dim3 gQK(8, BB * HH);
    qk_sums<<<gQK, 512, QKS_SMEM>>>(Qh, Kh, Eh, Iv);

    dim3 gPV(NN / 128, HH, BB);
    pv_fused<<<gPV, 256, PV_SMEM>>>(Eh, attn, Vt, Iv, Oh);

    dim3 gOut(8, 32);
    hgemm_out<<<gOut, 512, HG_SMEM>>>(Oh, WoT, out, bo);
}

// round 15
// speedup vs baseline: 1.6738x; 1.0063x over previous
#include <cuda_runtime.h>
#include <cuda_fp16.h>
#include <cstdint>
#include <cstddef>

#define BB   4
#define NN   1024
#define DIMC 1024
#define HH   16
#define DHD  64

// Scratch (no cudaMalloc allowed)
__device__ __half g_Xh [(size_t)BB * NN * DIMC];
__device__ __half g_WqT[(size_t)DIMC * DIMC];
__device__ __half g_WkT[(size_t)DIMC * DIMC];
__device__ __half g_WvT[(size_t)DIMC * DIMC];
__device__ __half g_WoT[(size_t)DIMC * DIMC];
__device__ __half g_Qh [(size_t)BB * NN * DIMC];
__device__ __half g_Kh [(size_t)BB * NN * DIMC];
__device__ __half g_Vt [(size_t)BB * DIMC * NN];   // [b*1024 + d][j]
__device__ __half g_Oh [(size_t)BB * NN * DIMC];
__device__ __half g_Eh [(size_t)BB * HH * NN * NN]; // unnormalized exp(S), fp16
__device__ float  g_inv[(size_t)BB * HH * NN];     // 1/rowsum

__device__ __forceinline__ void cp16(void* smem, const void* gmem) {
    uint32_t s = (uint32_t)__cvta_generic_to_shared(smem);
    asm volatile("cp.async.cg.shared.global [%0], [%1], 16;" :: "r"(s), "l"(gmem));
}
__device__ __forceinline__ void cp_commit() { asm volatile("cp.async.commit_group;"); }
__device__ __forceinline__ void cp_wait1()  { asm volatile("cp.async.wait_group 1;"); }
__device__ __forceinline__ void cp_wait2()  { asm volatile("cp.async.wait_group 2;"); }

#define MMA_F16(d, a0, a1, a2, a3, b0, b1)                                  \
    asm volatile(                                                           \
        "mma.sync.aligned.m16n8k16.row.col.f32.f16.f16.f32 "                \
        "{%0,%1,%2,%3}, {%4,%5,%6,%7}, {%8,%9}, {%0,%1,%2,%3};"             \
        : "+f"(d[0]), "+f"(d[1]), "+f"(d[2]), "+f"(d[3])                    \
        : "r"(a0), "r"(a1), "r"(a2), "r"(a3), "r"(b0), "r"(b1))

__device__ __forceinline__ void ldm4(uint32_t* r, const __half* p) {
    uint32_t a = (uint32_t)__cvta_generic_to_shared(p);
    asm volatile("ldmatrix.sync.aligned.m8n8.x4.shared.b16 {%0,%1,%2,%3}, [%4];"
        : "=r"(r[0]), "=r"(r[1]), "=r"(r[2]), "=r"(r[3]) : "r"(a));
}

__device__ __forceinline__ uint32_t h2u(__half2 h) {
    return *reinterpret_cast<uint32_t*>(&h);
}

// Scale a packed half2 by an fp32 factor with fp32 intermediate precision.
__device__ __forceinline__ uint32_t scale_h2(uint32_t u, float f) {
    __half2 h = *reinterpret_cast<__half2*>(&u);
    float2 fv = __half22float2(h);
    return h2u(__floats2half2_rn(fv.x * f, fv.y * f));
}

// ---------------------------------------------------------------------------
// prep: z=0: Xh = half(x); z=1..4: Wt[n][k] = half(W[k][n]).
// ---------------------------------------------------------------------------
__global__ __launch_bounds__(256) void prep(
    const float* __restrict__ x,
    const float* __restrict__ Wq, const float* __restrict__ Wk,
    const float* __restrict__ Wv, const float* __restrict__ Wo,
    __half* __restrict__ xh,
    __half* __restrict__ qt, __half* __restrict__ kt,
    __half* __restrict__ vt, __half* __restrict__ ot)
{
    int z = blockIdx.z;
    if (z == 0) {
        int bid = blockIdx.y * 32 + blockIdx.x;
        #pragma unroll
        for (int k = 0; k < 4; k++) {
            int i = bid * 1024 + k * 256 + threadIdx.x;
            float4 v = ((const float4*)x)[i];
            uint2 u;
            u.x = h2u(__floats2half2_rn(v.x, v.y));
            u.y = h2u(__floats2half2_rn(v.z, v.w));
            ((uint2*)xh)[i] = u;
        }
        return;
    }
    __shared__ float tile[32][33];
    const float* W = (z == 1) ? Wq : (z == 2) ? Wk : (z == 3) ? Wv : Wo;
    __half*      T = (z == 1) ? qt : (z == 2) ? kt : (z == 3) ? vt : ot;
    int bx = blockIdx.x * 32, by = blockIdx.y * 32;
    int tx = threadIdx.x & 31, ty = threadIdx.x >> 5;
    #pragma unroll
    for (int r = 0; r < 32; r += 8)
        tile[ty + r][tx] = W[(size_t)(by + ty + r) * DIMC + bx + tx];
    __syncthreads();
    #pragma unroll
    for (int r = 0; r < 32; r += 8)
        T[(size_t)(bx + ty + r) * DIMC + by + tx] = __float2half_rn(tile[tx][ty + r]);
}

// ---------------------------------------------------------------------------
// fp16 GEMM: C = A[M,K] @ Bt[N,K]^T. 128x128 tile, BK=32 halfs, 512 threads
// (16 warps, 4m x 4n, warp tile 32x32), 3-stage cp.async, ldmatrix operands.
// MODE 0: half out, scaled. MODE 1: float out + bias. MODE 2: Vt transposed.
// ---------------------------------------------------------------------------
#define HG_SMEM (3 * 2 * 5120 * 2)   // 61440 B

template<int MODE>
__device__ __forceinline__ void hgemm_body(
    const __half* __restrict__ A, const __half* __restrict__ Bt,
    void* __restrict__ Cout, const float* __restrict__ bias,
    __half* __restrict__ Vt, float outScale, int K, int Nc)
{
    extern __shared__ __half smh[];
    __half* As = smh;             // [3][128][40]
    __half* Bs = smh + 3 * 5120;  // [3][128][40]

    const int t     = threadIdx.x;
    const int wid   = t >> 5, lane = t & 31;
    const int group = lane >> 2, tig = lane & 3;
    const int wm    = (wid & 3) * 32;
    const int wn    = (wid >> 2) * 32;
    const int m0    = blockIdx.y * 128;
    const int n0    = blockIdx.x * 128;

    // ldmatrix per-lane offsets (halfs)
    const int la  = (lane & 15), lka = (lane >> 4) * 8;
    const int lb  = (lane & 7) + (lane >> 4) * 8;
    const int lkb = ((lane >> 3) & 1) * 8;

    auto load_stage = [&](int s, int k0) {
        __half* Ad = As + s * 5120;
        __half* Bd = Bs + s * 5120;
        int r = t >> 2, c8 = (t & 3) * 8;
        cp16(Ad + r * 40 + c8, A  + (size_t)(m0 + r) * K + k0 + c8);
        cp16(Bd + r * 40 + c8, Bt + (size_t)(n0 + r) * K + k0 + c8);
    };

    float acc[2][4][4] = {};
    load_stage(0, 0);  cp_commit();
    load_stage(1, 32); cp_commit();

    int s = 0;
    for (int k0 = 0; k0 < K; k0 += 32) {
        cp_wait1();
        __syncthreads();
        int s2 = (s >= 1) ? s - 1 : s + 2;
        if (k0 + 64 < K) load_stage(s2, k0 + 64);
        cp_commit();

        const __half* Ac = As + s * 5120;
        const __half* Bc = Bs + s * 5120;
        #pragma unroll
        for (int ks = 0; ks < 2; ks++) {
            int ko = ks * 16;
            uint32_t a[2][4], bb[2][4];
            ldm4(a[0],  Ac + (wm + la      ) * 40 + ko + lka);
            ldm4(a[1],  Ac + (wm + 16 + la ) * 40 + ko + lka);
            ldm4(bb[0], Bc + (wn + lb      ) * 40 + ko + lkb);
            ldm4(bb[1], Bc + (wn + 16 + lb ) * 40 + ko + lkb);
            #pragma unroll
            for (int np = 0; np < 2; np++) {
                #pragma unroll
                for (int mf = 0; mf < 2; mf++) {
                    MMA_F16(acc[mf][np * 2    ], a[mf][0], a[mf][1], a[mf][2], a[mf][3],
                            bb[np][0], bb[np][1]);
                    MMA_F16(acc[mf][np * 2 + 1], a[mf][0], a[mf][1], a[mf][2], a[mf][3],
                            bb[np][2], bb[np][3]);
                }
            }
        }
        s = (s == 2) ? 0 : s + 1;
        __syncthreads();
    }

    if (MODE == 2) {
        __half* st = smh;   // 128 x 132 halfs
        #pragma unroll
        for (int mf = 0; mf < 2; mf++) {
            #pragma unroll
            for (int nf = 0; nf < 4; nf++) {
                int row = wm + mf * 16 + group;
                int col = wn + nf * 8 + tig * 2;
                st[(col    ) * 132 + row    ] = __float2half_rn(acc[mf][nf][0]);
                st[(col + 1) * 132 + row    ] = __float2half_rn(acc[mf][nf][1]);
                st[(col    ) * 132 + row + 8] = __float2half_rn(acc[mf][nf][2]);
                st[(col + 1) * 132 + row + 8] = __float2half_rn(acc[mf][nf][3]);
            }
        }
        __syncthreads();
        int b  = m0 >> 10;
        int j0 = m0 & 1023;
        #pragma unroll
        for (int p = 0; p < 16; p++) {
            int i = p * 512 + t;
            int d = i >> 6, c2 = (i & 63) * 2;
            uint32_t v = *(const uint32_t*)(st + d * 132 + c2);
            *(uint32_t*)(Vt + ((size_t)b * DIMC + n0 + d) * NN + j0 + c2) = v;
        }
        return;
    }

    #pragma unroll
    for (int mf = 0; mf < 2; mf++) {
        #pragma unroll
        for (int nf = 0; nf < 4; nf++) {
            int row = m0 + wm + mf * 16 + group;
            int col = n0 + wn + nf * 8 + tig * 2;
            if (MODE == 0) {
                __half* C = (__half*)Cout;
                *(__half2*)(C + (size_t)row       * Nc + col) =
                    __floats2half2_rn(acc[mf][nf][0] * outScale, acc[mf][nf][1] * outScale);
                *(__half2*)(C + (size_t)(row + 8) * Nc + col) =
                    __floats2half2_rn(acc[mf][nf][2] * outScale, acc[mf][nf][3] * outScale);
            } else {
                float* C = (float*)Cout;
                float bx = bias[col], by = bias[col + 1];
                *(float2*)(C + (size_t)row       * Nc + col) =
                    make_float2(acc[mf][nf][0] + bx, acc[mf][nf][1] + by);
                *(float2*)(C + (size_t)(row + 8) * Nc + col) =
                    make_float2(acc[mf][nf][2] + bx, acc[mf][nf][3] + by);
            }
        }
    }
}

__global__ __launch_bounds__(512) void hgemm_qkv(
    const __half* __restrict__ x,
    const __half* __restrict__ WqT, const __half* __restrict__ WkT,
    const __half* __restrict__ WvT,
    __half* __restrict__ Qo, __half* __restrict__ Ko, __half* __restrict__ Vt)
{
    if (blockIdx.z == 0)
        hgemm_body<0>(x, WqT, Qo, nullptr, nullptr, 0.125f, DIMC, HH * DHD);
    else if (blockIdx.z == 1)
        hgemm_body<0>(x, WkT, Ko, nullptr, nullptr, 1.0f, DIMC, HH * DHD);
    else
        hgemm_body<2>(x, WvT, nullptr, nullptr, Vt, 1.0f, DIMC, HH * DHD);
}

__global__ __launch_bounds__(512) void hgemm_out(
    const __half* __restrict__ A, const __half* __restrict__ WoT,
    float* __restrict__ C, const float* __restrict__ bias)
{
    hgemm_body<1>(A, WoT, C, bias, nullptr, 1.0f, DIMC, DIMC);
}

// ---------------------------------------------------------------------------
// qk_sums: per (m-tile 128, head): S = Qs @ K^T via f16 MMA (ldmatrix B);
// stores E = exp(S) fp16 + 1/rowsum. Double-buffered cp.async K chunks.
// ---------------------------------------------------------------------------
#define QKS_SMEM (3 * 128 * 88 * 2)   // 67584 B

__global__ __launch_bounds__(512) void qk_sums(
    const __half* __restrict__ Q, const __half* __restrict__ Kt,
    __half* __restrict__ Eh, float* __restrict__ inv)
{
    extern __shared__ __half smq[];
    __half* Qs = smq;                 // [128][88]
    __half* Ks = smq + 128 * 88;      // [2][128][88]
    __shared__ float rowpart[128][4];

    const int t     = threadIdx.x;
    const int wid   = t >> 5, lane = t & 31;
    const int group = lane >> 2, tig = lane & 3;
    const int wm    = (wid & 3) * 32;
    const int wn    = (wid >> 2) * 32;
    const int m0    = blockIdx.x * 128;
    const int bh    = blockIdx.y;
    const int b     = bh >> 4, h = bh & 15;
    const size_t base = (size_t)b * NN * DIMC + (size_t)h * DHD;

    const int lb  = (lane & 7) + (lane >> 4) * 8;
    const int lkb = ((lane >> 3) & 1) * 8;

    auto loadK = [&](int buf, int c) {
        __half* Td = Ks + buf * (128 * 88);
        #pragma unroll
        for (int p = 0; p < 2; p++) {
            int i = p * 512 + t;
            int r = i >> 3, c8 = (i & 7) * 8;
            cp16(Td + r * 88 + c8, Kt + base + (size_t)(c * 128 + r) * DIMC + c8);
        }
    };

    #pragma unroll
    for (int p = 0; p < 2; p++) {
        int i = p * 512 + t;
        int r = i >> 3, c8 = (i & 7) * 8;
        cp16(Qs + r * 88 + c8, Q + base + (size_t)(m0 + r) * DIMC + c8);
    }
    cp_commit();
    loadK(0, 0); cp_commit();
    loadK(1, 1); cp_commit();

    cp_wait2();
    __syncthreads();

    // Q fragments via ldmatrix (one-time)
    uint32_t qa[2][4][4];
    {
        const int la  = (lane & 15), lka = (lane >> 4) * 8;
        #pragma unroll
        for (int ks = 0; ks < 4; ks++) {
            int ko = ks * 16;
            ldm4(qa[0][ks], Qs + (wm + la     ) * 88 + ko + lka);
            ldm4(qa[1][ks], Qs + (wm + 16 + la) * 88 + ko + lka);
        }
    }

    float sr[4] = {0.f, 0.f, 0.f, 0.f};

    for (int c = 0; c < 8; c++) {
        cp_wait1();
        __syncthreads();

        const __half* Tc = Ks + (c & 1) * (128 * 88);
        float acc[2][4][4] = {};
        #pragma unroll
        for (int ks = 0; ks < 4; ks++) {
            int ko = ks * 16;
            uint32_t bb[2][4];
            ldm4(bb[0], Tc + (wn + lb     ) * 88 + ko + lkb);
            ldm4(bb[1], Tc + (wn + 16 + lb) * 88 + ko + lkb);
            #pragma unroll
            for (int np = 0; np < 2; np++) {
                #pragma unroll
                for (int mf = 0; mf < 2; mf++) {
                    MMA_F16(acc[mf][np * 2    ], qa[mf][ks][0], qa[mf][ks][1],
                            qa[mf][ks][2], qa[mf][ks][3], bb[np][0], bb[np][1]);
                    MMA_F16(acc[mf][np * 2 + 1], qa[mf][ks][0], qa[mf][ks][1],
                            qa[mf][ks][2], qa[mf][ks][3], bb[np][2], bb[np][3]);
                }
            }
        }

        __syncthreads();
        if (c < 6) loadK(c & 1, c + 2);
        cp_commit();

        __half* Sb = Eh + ((size_t)bh * NN + m0) * NN + c * 128;
        #pragma unroll
        for (int mf = 0; mf < 2; mf++) {
            #pragma unroll
            for (int nf = 0; nf < 4; nf++) {
                float e0 = __expf(acc[mf][nf][0]);
                float e1 = __expf(acc[mf][nf][1]);
                float e2 = __expf(acc[mf][nf][2]);
                float e3 = __expf(acc[mf][nf][3]);
                sr[mf * 2    ] += e0 + e1;
                sr[mf * 2 + 1] += e2 + e3;
                int row = wm + mf * 16 + group;
                int col = wn + nf * 8 + tig * 2;
                *(__half2*)(Sb + (size_t)row       * NN + col) = __floats2half2_rn(e0, e1);
                *(__half2*)(Sb + (size_t)(row + 8) * NN + col) = __floats2half2_rn(e2, e3);
            }
        }
    }

    #pragma unroll
    for (int i = 0; i < 4; i++) {
        sr[i] += __shfl_xor_sync(0xffffffffu, sr[i], 1);
        sr[i] += __shfl_xor_sync(0xffffffffu, sr[i], 2);
    }
    if (tig == 0) {
        #pragma unroll
        for (int mf = 0; mf < 2; mf++) {
            rowpart[wm + mf * 16 + group    ][wid >> 2] = sr[mf * 2    ];
            rowpart[wm + mf * 16 + group + 8][wid >> 2] = sr[mf * 2 + 1];
        }
    }
    __syncthreads();
    if (t < 128) {
        float ssum = rowpart[t][0] + rowpart[t][1] + rowpart[t][2] + rowpart[t][3];
        inv[(size_t)bh * NN + m0 + t] = 1.f / ssum;
    }
}

// ---------------------------------------------------------------------------
// pv_fused: O = (E * inv) @ V ; writes normalized attn (fp32) from staged
// fp16 E. 128x64 tile, 256 threads (8 warps: 4m x 2n), BK=16, 3-stage
// cp.async, ldmatrix operands.
// ---------------------------------------------------------------------------
#define PV_SMEM ((3 * 128 * 24 + 3 * 64 * 24) * 2)   // 27648 B

__global__ __launch_bounds__(256) void pv_fused(
    const __half* __restrict__ Eh, float* __restrict__ attn,
    const __half* __restrict__ Vt,
    const float* __restrict__ inv, __half* __restrict__ Oh)
{
    extern __shared__ __half smv[];
    __half* As = smv;                  // [3][128][24]
    __half* Bs = smv + 3 * 128 * 24;   // [3][64][24]

    const int t     = threadIdx.x;
    const int wid   = t >> 5, lane = t & 31;
    const int group = lane >> 2, tig = lane & 3;
    const int wm    = (wid & 3) * 32;
    const int wn    = (wid >> 2) * 32;
    const int m0    = blockIdx.x * 128;
    const int h     = blockIdx.y, b = blockIdx.z;

    const int la  = (lane & 15), lka = (lane >> 4) * 8;
    const int lb  = (lane & 7) + (lane >> 4) * 8;
    const int lkb = ((lane >> 3) & 1) * 8;

    const size_t rowbase = ((size_t)b * HH + h) * NN + m0;
    const __half* Eb  = Eh + rowbase * NN;
    float*        Pb  = attn + rowbase * NN;
    const __half* Vtb = Vt + ((size_t)b * DIMC + h * DHD) * NN;
    __half*       Ob  = Oh + (size_t)b * NN * DIMC + (size_t)h * DHD;

    float fi[4];
    #pragma unroll
    for (int mf = 0; mf < 2; mf++) {
        fi[mf * 2    ] = inv[rowbase + wm + mf * 16 + group    ];
        fi[mf * 2 + 1] = inv[rowbase + wm + mf * 16 + group + 8];
    }
    float wi[2];
    #pragma unroll
    for (int l = 0; l < 2; l++) wi[l] = inv[rowbase + ((l * 256 + t) >> 2)];

    auto load_stage = [&](int s, int k0) {
        __half* Ad = As + s * (128 * 24);
        __half* Bd = Bs + s * (64 * 24);
        {
            int r = t >> 1, c8 = (t & 1) * 8;
            cp16(Ad + r * 24 + c8, Eb + (size_t)r * NN + k0 + c8);
        }
        if (t < 128) {
            int r = t >> 1, c8 = (t & 1) * 8;
            cp16(Bd + r * 24 + c8, Vtb + (size_t)r * NN + k0 + c8);
        }
    };

    float acc[2][4][4] = {};

    load_stage(0, 0);  cp_commit();
    load_stage(1, 16); cp_commit();

    int s = 0;
    for (int k0 = 0; k0 < NN; k0 += 16) {
        cp_wait1();
        __syncthreads();
        int s2 = (s >= 1) ? s - 1 : s + 2;
        if (k0 + 32 < NN) load_stage(s2, k0 + 32);
        cp_commit();

        const __half* Ac = As + s * (128 * 24);
        const __half* Bc = Bs + s * (64 * 24);

        // normalized attn write (fp32) from staged fp16 E
        #pragma unroll
        for (int l = 0; l < 2; l++) {
            int c = l * 256 + t;
            int r = c >> 2, k4 = (c & 3) * 4;
            const __half* src = Ac + r * 24 + k4;
            __half2 h0 = *(const __half2*)(src);
            __half2 h1 = *(const __half2*)(src + 2);
            float wl = wi[l];
            float4 v;
            v.x = __low2float(h0) * wl; v.y = __high2float(h0) * wl;
            v.z = __low2float(h1) * wl; v.w = __high2float(h1) * wl;
            *(float4*)(Pb + (size_t)r * NN + k0 + k4) = v;
        }

        uint32_t a[2][4], bb[2][4];
        #pragma unroll
        for (int mf = 0; mf < 2; mf++) {
            ldm4(a[mf], Ac + (wm + mf * 16 + la) * 24 + lka);
            float f0 = fi[mf * 2], f1 = fi[mf * 2 + 1];
            a[mf][0] = scale_h2(a[mf][0], f0);
            a[mf][1] = scale_h2(a[mf][1], f1);
            a[mf][2] = scale_h2(a[mf][2], f0);
            a[mf][3] = scale_h2(a[mf][3], f1);
        }
        ldm4(bb[0], Bc + (wn + lb     ) * 24 + lkb);
        ldm4(bb[1], Bc + (wn + 16 + lb) * 24 + lkb);
        #pragma unroll
        for (int np = 0; np < 2; np++) {
            #pragma unroll
            for (int mf = 0; mf < 2; mf++) {
                MMA_F16(acc[mf][np * 2    ], a[mf][0], a[mf][1], a[mf][2], a[mf][3],
                        bb[np][0], bb[np][1]);
                MMA_F16(acc[mf][np * 2 + 1], a[mf][0], a[mf][1], a[mf][2], a[mf][3],
                        bb[np][2], bb[np][3]);
            }
        }
        s = (s == 2) ? 0 : s + 1;
        __syncthreads();
    }

    #pragma unroll
    for (int mf = 0; mf < 2; mf++) {
        #pragma unroll
        for (int nf = 0; nf < 4; nf++) {
            int row = m0 + wm + mf * 16 + group;
            int col = wn + nf * 8 + tig * 2;
            *(__half2*)(Ob + (size_t)row       * DIMC + col) =
                __floats2half2_rn(acc[mf][nf][0], acc[mf][nf][1]);
            *(__half2*)(Ob + (size_t)(row + 8) * DIMC + col) =
                __floats2half2_rn(acc[mf][nf][2], acc[mf][nf][3]);
        }
    }
}

// ---------------------------------------------------------------------------
extern "C" void kernel_launch(void* const* d_in, const int* in_sizes, int n_in,
                              void* d_out, int out_size)
{
    const float* x  = (const float*)d_in[0];
    const float* Wq = (const float*)d_in[1];
    const float* Wk = (const float*)d_in[2];
    const float* Wv = (const float*)d_in[3];
    const float* Wo = (const float*)d_in[4];
    const float* bo = (const float*)d_in[5];

    float* out  = (float*)d_out;
    float* attn = out + (size_t)BB * NN * DIMC;

    __half *Xh, *WqT, *WkT, *WvT, *WoT, *Qh, *Kh, *Vt, *Oh, *Eh;
    float* Iv;
    cudaGetSymbolAddress((void**)&Xh,  g_Xh);
    cudaGetSymbolAddress((void**)&WqT, g_WqT);
    cudaGetSymbolAddress((void**)&WkT, g_WkT);
    cudaGetSymbolAddress((void**)&WvT, g_WvT);
    cudaGetSymbolAddress((void**)&WoT, g_WoT);
    cudaGetSymbolAddress((void**)&Qh,  g_Qh);
    cudaGetSymbolAddress((void**)&Kh,  g_Kh);
    cudaGetSymbolAddress((void**)&Vt,  g_Vt);
    cudaGetSymbolAddress((void**)&Oh,  g_Oh);
    cudaGetSymbolAddress((void**)&Eh,  g_Eh);
    cudaGetSymbolAddress((void**)&Iv,  g_inv);

    cudaFuncSetAttribute(hgemm_qkv, cudaFuncAttributeMaxDynamicSharedMemorySize, HG_SMEM);
    cudaFuncSetAttribute(hgemm_out, cudaFuncAttributeMaxDynamicSharedMemorySize, HG_SMEM);
    cudaFuncSetAttribute(qk_sums,   cudaFuncAttributeMaxDynamicSharedMemorySize, QKS_SMEM);
    cudaFuncSetAttribute(pv_fused,  cudaFuncAttributeMaxDynamicSharedMemorySize, PV_SMEM);

    dim3 gPrep(32, 32, 5);
    prep<<<gPrep, 256>>>(x, Wq, Wk, Wv, Wo, Xh, WqT, WkT, WvT, WoT);

    dim3 gQKV(8, 32, 3);
    hgemm_qkv<<<gQKV, 512, HG_SMEM>>>(Xh, WqT, WkT, WvT, Qh, Kh, Vt);

    dim3 gQK(8, BB * HH);
    qk_sums<<<gQK, 512, QKS_SMEM>>>(Qh, Kh, Eh, Iv);

    dim3 gPV(NN / 128, HH, BB);
    pv_fused<<<gPV, 256, PV_SMEM>>>(Eh, attn, Vt, Iv, Oh);

    dim3 gOut(8, 32);
    hgemm_out<<<gOut, 512, HG_SMEM>>>(Oh, WoT, out, bo);
}

// round 16
// speedup vs baseline: 1.7528x; 1.0471x over previous
#include <cuda_runtime.h>
#include <cuda_fp16.h>
#include <cstdint>
#include <cstddef>

#define BB   4
#define NN   1024
#define DIMC 1024
#define HH   16
#define DHD  64

// Scratch (no cudaMalloc allowed)
__device__ __half g_Xh [(size_t)BB * NN * DIMC];
__device__ __half g_WqT[(size_t)DIMC * DIMC];
__device__ __half g_WkT[(size_t)DIMC * DIMC];
__device__ __half g_WvT[(size_t)DIMC * DIMC];
__device__ __half g_WoT[(size_t)DIMC * DIMC];
__device__ __half g_Qh [(size_t)BB * NN * DIMC];
__device__ __half g_Kh [(size_t)BB * NN * DIMC];
__device__ __half g_Vt [(size_t)BB * DIMC * NN];   // [b*1024 + d][j]
__device__ __half g_Oh [(size_t)BB * NN * DIMC];
__device__ __half g_Eh [(size_t)BB * HH * NN * NN]; // unnormalized exp(S), fp16
__device__ float  g_inv[(size_t)BB * HH * NN];     // 1/rowsum

__device__ __forceinline__ void cp16(void* smem, const void* gmem) {
    uint32_t s = (uint32_t)__cvta_generic_to_shared(smem);
    asm volatile("cp.async.cg.shared.global [%0], [%1], 16;" :: "r"(s), "l"(gmem));
}
__device__ __forceinline__ void cp_commit() { asm volatile("cp.async.commit_group;"); }
__device__ __forceinline__ void cp_wait1()  { asm volatile("cp.async.wait_group 1;"); }
__device__ __forceinline__ void cp_wait2()  { asm volatile("cp.async.wait_group 2;"); }

#define MMA_F16(d, a0, a1, a2, a3, b0, b1)                                  \
    asm volatile(                                                           \
        "mma.sync.aligned.m16n8k16.row.col.f32.f16.f16.f32 "                \
        "{%0,%1,%2,%3}, {%4,%5,%6,%7}, {%8,%9}, {%0,%1,%2,%3};"             \
        : "+f"(d[0]), "+f"(d[1]), "+f"(d[2]), "+f"(d[3])                    \
        : "r"(a0), "r"(a1), "r"(a2), "r"(a3), "r"(b0), "r"(b1))

__device__ __forceinline__ void ldm4(uint32_t* r, const __half* p) {
    uint32_t a = (uint32_t)__cvta_generic_to_shared(p);
    asm volatile("ldmatrix.sync.aligned.m8n8.x4.shared.b16 {%0,%1,%2,%3}, [%4];"
        : "=r"(r[0]), "=r"(r[1]), "=r"(r[2]), "=r"(r[3]) : "r"(a));
}

__device__ __forceinline__ uint32_t h2u(__half2 h) {
    return *reinterpret_cast<uint32_t*>(&h);
}

// Scale a packed half2 by an fp32 factor with fp32 intermediate precision.
__device__ __forceinline__ uint32_t scale_h2(uint32_t u, float f) {
    __half2 h = *reinterpret_cast<__half2*>(&u);
    float2 fv = __half22float2(h);
    return h2u(__floats2half2_rn(fv.x * f, fv.y * f));
}

// ---------------------------------------------------------------------------
// prep: z=0: Xh = half(x); z=1..4: Wt[n][k] = half(W[k][n]).
// ---------------------------------------------------------------------------
__global__ __launch_bounds__(256) void prep(
    const float* __restrict__ x,
    const float* __restrict__ Wq, const float* __restrict__ Wk,
    const float* __restrict__ Wv, const float* __restrict__ Wo,
    __half* __restrict__ xh,
    __half* __restrict__ qt, __half* __restrict__ kt,
    __half* __restrict__ vt, __half* __restrict__ ot)
{
    int z = blockIdx.z;
    if (z == 0) {
        int bid = blockIdx.y * 32 + blockIdx.x;
        #pragma unroll
        for (int k = 0; k < 4; k++) {
            int i = bid * 1024 + k * 256 + threadIdx.x;
            float4 v = ((const float4*)x)[i];
            uint2 u;
            u.x = h2u(__floats2half2_rn(v.x, v.y));
            u.y = h2u(__floats2half2_rn(v.z, v.w));
            ((uint2*)xh)[i] = u;
        }
        return;
    }
    __shared__ float tile[32][33];
    const float* W = (z == 1) ? Wq : (z == 2) ? Wk : (z == 3) ? Wv : Wo;
    __half*      T = (z == 1) ? qt : (z == 2) ? kt : (z == 3) ? vt : ot;
    int bx = blockIdx.x * 32, by = blockIdx.y * 32;
    int tx = threadIdx.x & 31, ty = threadIdx.x >> 5;
    #pragma unroll
    for (int r = 0; r < 32; r += 8)
        tile[ty + r][tx] = W[(size_t)(by + ty + r) * DIMC + bx + tx];
    __syncthreads();
    #pragma unroll
    for (int r = 0; r < 32; r += 8)
        T[(size_t)(bx + ty + r) * DIMC + by + tx] = __float2half_rn(tile[tx][ty + r]);
}

// ---------------------------------------------------------------------------
// fp16 GEMM: C = A[M,K] @ Bt[N,K]^T. 128x128 tile, BK=32 halfs, 512 threads
// (16 warps, 4m x 4n, warp tile 32x32), 3-stage cp.async, ldmatrix operands.
// MODE 0: half out, scaled. MODE 1: float out + bias. MODE 2: Vt transposed.
// ---------------------------------------------------------------------------
#define HG_SMEM (3 * 2 * 5120 * 2)   // 61440 B

template<int MODE>
__device__ __forceinline__ void hgemm_body(
    const __half* __restrict__ A, const __half* __restrict__ Bt,
    void* __restrict__ Cout, const float* __restrict__ bias,
    __half* __restrict__ Vt, float outScale, int K, int Nc)
{
    extern __shared__ __half smh[];
    __half* As = smh;             // [3][128][40]
    __half* Bs = smh + 3 * 5120;  // [3][128][40]

    const int t     = threadIdx.x;
    const int wid   = t >> 5, lane = t & 31;
    const int group = lane >> 2, tig = lane & 3;
    const int wm    = (wid & 3) * 32;
    const int wn    = (wid >> 2) * 32;
    const int m0    = blockIdx.y * 128;
    const int n0    = blockIdx.x * 128;

    const int la  = (lane & 15), lka = (lane >> 4) * 8;
    const int lb  = (lane & 7) + (lane >> 4) * 8;
    const int lkb = ((lane >> 3) & 1) * 8;

    auto load_stage = [&](int s, int k0) {
        __half* Ad = As + s * 5120;
        __half* Bd = Bs + s * 5120;
        int r = t >> 2, c8 = (t & 3) * 8;
        cp16(Ad + r * 40 + c8, A  + (size_t)(m0 + r) * K + k0 + c8);
        cp16(Bd + r * 40 + c8, Bt + (size_t)(n0 + r) * K + k0 + c8);
    };

    float acc[2][4][4] = {};
    load_stage(0, 0);  cp_commit();
    load_stage(1, 32); cp_commit();

    int s = 0;
    for (int k0 = 0; k0 < K; k0 += 32) {
        cp_wait1();
        __syncthreads();
        int s2 = (s >= 1) ? s - 1 : s + 2;
        if (k0 + 64 < K) load_stage(s2, k0 + 64);
        cp_commit();

        const __half* Ac = As + s * 5120;
        const __half* Bc = Bs + s * 5120;
        #pragma unroll
        for (int ks = 0; ks < 2; ks++) {
            int ko = ks * 16;
            uint32_t a[2][4], bb[2][4];
            ldm4(a[0],  Ac + (wm + la      ) * 40 + ko + lka);
            ldm4(a[1],  Ac + (wm + 16 + la ) * 40 + ko + lka);
            ldm4(bb[0], Bc + (wn + lb      ) * 40 + ko + lkb);
            ldm4(bb[1], Bc + (wn + 16 + lb ) * 40 + ko + lkb);
            #pragma unroll
            for (int np = 0; np < 2; np++) {
                #pragma unroll
                for (int mf = 0; mf < 2; mf++) {
                    MMA_F16(acc[mf][np * 2    ], a[mf][0], a[mf][1], a[mf][2], a[mf][3],
                            bb[np][0], bb[np][1]);
                    MMA_F16(acc[mf][np * 2 + 1], a[mf][0], a[mf][1], a[mf][2], a[mf][3],
                            bb[np][2], bb[np][3]);
                }
            }
        }
        s = (s == 2) ? 0 : s + 1;
        __syncthreads();
    }

    if (MODE == 2) {
        __half* st = smh;   // 128 x 132 halfs
        #pragma unroll
        for (int mf = 0; mf < 2; mf++) {
            #pragma unroll
            for (int nf = 0; nf < 4; nf++) {
                int row = wm + mf * 16 + group;
                int col = wn + nf * 8 + tig * 2;
                st[(col    ) * 132 + row    ] = __float2half_rn(acc[mf][nf][0]);
                st[(col + 1) * 132 + row    ] = __float2half_rn(acc[mf][nf][1]);
                st[(col    ) * 132 + row + 8] = __float2half_rn(acc[mf][nf][2]);
                st[(col + 1) * 132 + row + 8] = __float2half_rn(acc[mf][nf][3]);
            }
        }
        __syncthreads();
        int b  = m0 >> 10;
        int j0 = m0 & 1023;
        #pragma unroll
        for (int p = 0; p < 16; p++) {
            int i = p * 512 + t;
            int d = i >> 6, c2 = (i & 63) * 2;
            uint32_t v = *(const uint32_t*)(st + d * 132 + c2);
            *(uint32_t*)(Vt + ((size_t)b * DIMC + n0 + d) * NN + j0 + c2) = v;
        }
        return;
    }

    #pragma unroll
    for (int mf = 0; mf < 2; mf++) {
        #pragma unroll
        for (int nf = 0; nf < 4; nf++) {
            int row = m0 + wm + mf * 16 + group;
            int col = n0 + wn + nf * 8 + tig * 2;
            if (MODE == 0) {
                __half* C = (__half*)Cout;
                *(__half2*)(C + (size_t)row       * Nc + col) =
                    __floats2half2_rn(acc[mf][nf][0] * outScale, acc[mf][nf][1] * outScale);
                *(__half2*)(C + (size_t)(row + 8) * Nc + col) =
                    __floats2half2_rn(acc[mf][nf][2] * outScale, acc[mf][nf][3] * outScale);
            } else {
                float* C = (float*)Cout;
                float bx = bias[col], by = bias[col + 1];
                *(float2*)(C + (size_t)row       * Nc + col) =
                    make_float2(acc[mf][nf][0] + bx, acc[mf][nf][1] + by);
                *(float2*)(C + (size_t)(row + 8) * Nc + col) =
                    make_float2(acc[mf][nf][2] + bx, acc[mf][nf][3] + by);
            }
        }
    }
}

__global__ __launch_bounds__(512) void hgemm_qkv(
    const __half* __restrict__ x,
    const __half* __restrict__ WqT, const __half* __restrict__ WkT,
    const __half* __restrict__ WvT,
    __half* __restrict__ Qo, __half* __restrict__ Ko, __half* __restrict__ Vt)
{
    if (blockIdx.z == 0)
        hgemm_body<0>(x, WqT, Qo, nullptr, nullptr, 0.125f, DIMC, HH * DHD);
    else if (blockIdx.z == 1)
        hgemm_body<0>(x, WkT, Ko, nullptr, nullptr, 1.0f, DIMC, HH * DHD);
    else
        hgemm_body<2>(x, WvT, nullptr, nullptr, Vt, 1.0f, DIMC, HH * DHD);
}

__global__ __launch_bounds__(512) void hgemm_out(
    const __half* __restrict__ A, const __half* __restrict__ WoT,
    float* __restrict__ C, const float* __restrict__ bias)
{
    hgemm_body<1>(A, WoT, C, bias, nullptr, 1.0f, DIMC, DIMC);
}

// ---------------------------------------------------------------------------
// qk_sums: per (m-tile 128, head): S = Qs @ K^T via f16 MMA (ldmatrix);
// stores E = exp(S) fp16 + 1/rowsum. Double-buffered cp.async K chunks.
// ---------------------------------------------------------------------------
#define QKS_SMEM (3 * 128 * 88 * 2)   // 67584 B

__global__ __launch_bounds__(512) void qk_sums(
    const __half* __restrict__ Q, const __half* __restrict__ Kt,
    __half* __restrict__ Eh, float* __restrict__ inv)
{
    extern __shared__ __half smq[];
    __half* Qs = smq;                 // [128][88]
    __half* Ks = smq + 128 * 88;      // [2][128][88]
    __shared__ float rowpart[128][4];

    const int t     = threadIdx.x;
    const int wid   = t >> 5, lane = t & 31;
    const int group = lane >> 2, tig = lane & 3;
    const int wm    = (wid & 3) * 32;
    const int wn    = (wid >> 2) * 32;
    const int m0    = blockIdx.x * 128;
    const int bh    = blockIdx.y;
    const int b     = bh >> 4, h = bh & 15;
    const size_t base = (size_t)b * NN * DIMC + (size_t)h * DHD;

    const int lb  = (lane & 7) + (lane >> 4) * 8;
    const int lkb = ((lane >> 3) & 1) * 8;

    auto loadK = [&](int buf, int c) {
        __half* Td = Ks + buf * (128 * 88);
        #pragma unroll
        for (int p = 0; p < 2; p++) {
            int i = p * 512 + t;
            int r = i >> 3, c8 = (i & 7) * 8;
            cp16(Td + r * 88 + c8, Kt + base + (size_t)(c * 128 + r) * DIMC + c8);
        }
    };

    #pragma unroll
    for (int p = 0; p < 2; p++) {
        int i = p * 512 + t;
        int r = i >> 3, c8 = (i & 7) * 8;
        cp16(Qs + r * 88 + c8, Q + base + (size_t)(m0 + r) * DIMC + c8);
    }
    cp_commit();
    loadK(0, 0); cp_commit();
    loadK(1, 1); cp_commit();

    cp_wait2();
    __syncthreads();

    uint32_t qa[2][4][4];
    {
        const int la  = (lane & 15), lka = (lane >> 4) * 8;
        #pragma unroll
        for (int ks = 0; ks < 4; ks++) {
            int ko = ks * 16;
            ldm4(qa[0][ks], Qs + (wm + la     ) * 88 + ko + lka);
            ldm4(qa[1][ks], Qs + (wm + 16 + la) * 88 + ko + lka);
        }
    }

    float sr[4] = {0.f, 0.f, 0.f, 0.f};

    for (int c = 0; c < 8; c++) {
        cp_wait1();
        __syncthreads();

        const __half* Tc = Ks + (c & 1) * (128 * 88);
        float acc[2][4][4] = {};
        #pragma unroll
        for (int ks = 0; ks < 4; ks++) {
            int ko = ks * 16;
            uint32_t bb[2][4];
            ldm4(bb[0], Tc + (wn + lb     ) * 88 + ko + lkb);
            ldm4(bb[1], Tc + (wn + 16 + lb) * 88 + ko + lkb);
            #pragma unroll
            for (int np = 0; np < 2; np++) {
                #pragma unroll
                for (int mf = 0; mf < 2; mf++) {
                    MMA_F16(acc[mf][np * 2    ], qa[mf][ks][0], qa[mf][ks][1],
                            qa[mf][ks][2], qa[mf][ks][3], bb[np][0], bb[np][1]);
                    MMA_F16(acc[mf][np * 2 + 1], qa[mf][ks][0], qa[mf][ks][1],
                            qa[mf][ks][2], qa[mf][ks][3], bb[np][2], bb[np][3]);
                }
            }
        }

        __syncthreads();
        if (c < 6) loadK(c & 1, c + 2);
        cp_commit();

        __half* Sb = Eh + ((size_t)bh * NN + m0) * NN + c * 128;
        #pragma unroll
        for (int mf = 0; mf < 2; mf++) {
            #pragma unroll
            for (int nf = 0; nf < 4; nf++) {
                float e0 = __expf(acc[mf][nf][0]);
                float e1 = __expf(acc[mf][nf][1]);
                float e2 = __expf(acc[mf][nf][2]);
                float e3 = __expf(acc[mf][nf][3]);
                sr[mf * 2    ] += e0 + e1;
                sr[mf * 2 + 1] += e2 + e3;
                int row = wm + mf * 16 + group;
                int col = wn + nf * 8 + tig * 2;
                *(__half2*)(Sb + (size_t)row       * NN + col) = __floats2half2_rn(e0, e1);
                *(__half2*)(Sb + (size_t)(row + 8) * NN + col) = __floats2half2_rn(e2, e3);
            }
        }
    }

    #pragma unroll
    for (int i = 0; i < 4; i++) {
        sr[i] += __shfl_xor_sync(0xffffffffu, sr[i], 1);
        sr[i] += __shfl_xor_sync(0xffffffffu, sr[i], 2);
    }
    if (tig == 0) {
        #pragma unroll
        for (int mf = 0; mf < 2; mf++) {
            rowpart[wm + mf * 16 + group    ][wid >> 2] = sr[mf * 2    ];
            rowpart[wm + mf * 16 + group + 8][wid >> 2] = sr[mf * 2 + 1];
        }
    }
    __syncthreads();
    if (t < 128) {
        float ssum = rowpart[t][0] + rowpart[t][1] + rowpart[t][2] + rowpart[t][3];
        inv[(size_t)bh * NN + m0 + t] = 1.f / ssum;
    }
}

// ---------------------------------------------------------------------------
// pv_fused: O = (E * inv) @ V ; writes normalized attn (fp32) from staged
// fp16 E. 128x64 tile, 256 threads (8 warps: 4m x 2n), BK=32, 3-stage
// cp.async, scalar fragment loads (stride 40 halfs: conflict-free).
// ---------------------------------------------------------------------------
#define PV_SMEM (3 * (128 * 40 + 64 * 40) * 2)   // 46080 B

__global__ __launch_bounds__(256) void pv_fused(
    const __half* __restrict__ Eh, float* __restrict__ attn,
    const __half* __restrict__ Vt,
    const float* __restrict__ inv, __half* __restrict__ Oh)
{
    extern __shared__ __half smv[];
    __half* As = smv;                  // [3][128][40]
    __half* Bs = smv + 3 * 128 * 40;   // [3][64][40]

    const int t     = threadIdx.x;
    const int wid   = t >> 5, lane = t & 31;
    const int group = lane >> 2, tig = lane & 3;
    const int wm    = (wid & 3) * 32;
    const int wn    = (wid >> 2) * 32;
    const int m0    = blockIdx.x * 128;
    const int h     = blockIdx.y, b = blockIdx.z;

    const size_t rowbase = ((size_t)b * HH + h) * NN + m0;
    const __half* Eb  = Eh + rowbase * NN;
    float*        Pb  = attn + rowbase * NN;
    const __half* Vtb = Vt + ((size_t)b * DIMC + h * DHD) * NN;
    __half*       Ob  = Oh + (size_t)b * NN * DIMC + (size_t)h * DHD;

    float fi[4];
    #pragma unroll
    for (int mf = 0; mf < 2; mf++) {
        fi[mf * 2    ] = inv[rowbase + wm + mf * 16 + group    ];
        fi[mf * 2 + 1] = inv[rowbase + wm + mf * 16 + group + 8];
    }
    float wi[4];
    #pragma unroll
    for (int l = 0; l < 4; l++) wi[l] = inv[rowbase + ((l * 256 + t) >> 3)];

    auto load_stage = [&](int s, int k0) {
        __half* Ad = As + s * (128 * 40);
        __half* Bd = Bs + s * (64 * 40);
        #pragma unroll
        for (int l = 0; l < 2; l++) {
            int i = l * 256 + t;
            int r = i >> 2, c8 = (i & 3) * 8;
            cp16(Ad + r * 40 + c8, Eb + (size_t)r * NN + k0 + c8);
        }
        {
            int r = t >> 2, c8 = (t & 3) * 8;
            cp16(Bd + r * 40 + c8, Vtb + (size_t)r * NN + k0 + c8);
        }
    };

    float acc[2][4][4] = {};

    load_stage(0, 0);  cp_commit();
    load_stage(1, 32); cp_commit();

    int s = 0;
    for (int k0 = 0; k0 < NN; k0 += 32) {
        cp_wait1();
        __syncthreads();
        int s2 = (s >= 1) ? s - 1 : s + 2;
        if (k0 + 64 < NN) load_stage(s2, k0 + 64);
        cp_commit();

        const __half* Ac = As + s * (128 * 40);
        const __half* Bc = Bs + s * (64 * 40);

        // normalized attn write (fp32) from staged fp16 E: 128 rows x 32 cols
        #pragma unroll
        for (int l = 0; l < 4; l++) {
            int i = l * 256 + t;
            int r = i >> 3, k4 = (i & 7) * 4;
            const __half* src = Ac + r * 40 + k4;
            __half2 h0 = *(const __half2*)(src);
            __half2 h1 = *(const __half2*)(src + 2);
            float wl = wi[l];
            float4 v;
            v.x = __low2float(h0) * wl; v.y = __high2float(h0) * wl;
            v.z = __low2float(h1) * wl; v.w = __high2float(h1) * wl;
            *(float4*)(Pb + (size_t)r * NN + k0 + k4) = v;
        }

        #pragma unroll
        for (int ks = 0; ks < 2; ks++) {
            int ko = ks * 16;
            uint32_t a[2][4];
            #pragma unroll
            for (int mf = 0; mf < 2; mf++) {
                const __half* Ar = Ac + (wm + mf * 16 + group) * 40 + 2 * tig + ko;
                float f0 = fi[mf * 2], f1 = fi[mf * 2 + 1];
                a[mf][0] = scale_h2(*(const uint32_t*)(Ar      ), f0);
                a[mf][1] = scale_h2(*(const uint32_t*)(Ar + 320), f1);   // row +8
                a[mf][2] = scale_h2(*(const uint32_t*)(Ar +   8), f0);   // k +8
                a[mf][3] = scale_h2(*(const uint32_t*)(Ar + 328), f1);
            }
            #pragma unroll
            for (int nf = 0; nf < 4; nf++) {
                const __half* Br = Bc + (wn + nf * 8 + group) * 40 + 2 * tig + ko;
                uint32_t b0 = *(const uint32_t*)(Br);
                uint32_t b1 = *(const uint32_t*)(Br + 8);
                #pragma unroll
                for (int mf = 0; mf < 2; mf++)
                    MMA_F16(acc[mf][nf], a[mf][0], a[mf][1], a[mf][2], a[mf][3], b0, b1);
            }
        }
        s = (s == 2) ? 0 : s + 1;
        __syncthreads();
    }

    #pragma unroll
    for (int mf = 0; mf < 2; mf++) {
        #pragma unroll
        for (int nf = 0; nf < 4; nf++) {
            int row = m0 + wm + mf * 16 + group;
            int col = wn + nf * 8 + tig * 2;
            *(__half2*)(Ob + (size_t)row       * DIMC + col) =
                __floats2half2_rn(acc[mf][nf][0], acc[mf][nf][1]);
            *(__half2*)(Ob + (size_t)(row + 8) * DIMC + col) =
                __floats2half2_rn(acc[mf][nf][2], acc[mf][nf][3]);
        }
    }
}

// ---------------------------------------------------------------------------
extern "C" void kernel_launch(void* const* d_in, const int* in_sizes, int n_in,
                              void* d_out, int out_size)
{
    const float* x  = (const float*)d_in[0];
    const float* Wq = (const float*)d_in[1];
    const float* Wk = (const float*)d_in[2];
    const float* Wv = (const float*)d_in[3];
    const float* Wo = (const float*)d_in[4];
    const float* bo = (const float*)d_in[5];

    float* out  = (float*)d_out;
    float* attn = out + (size_t)BB * NN * DIMC;

    __half *Xh, *WqT, *WkT, *WvT, *WoT, *Qh, *Kh, *Vt, *Oh, *Eh;
    float* Iv;
    cudaGetSymbolAddress((void**)&Xh,  g_Xh);
    cudaGetSymbolAddress((void**)&WqT, g_WqT);
    cudaGetSymbolAddress((void**)&WkT, g_WkT);
    cudaGetSymbolAddress((void**)&WvT, g_WvT);
    cudaGetSymbolAddress((void**)&WoT, g_WoT);
    cudaGetSymbolAddress((void**)&Qh,  g_Qh);
    cudaGetSymbolAddress((void**)&Kh,  g_Kh);
    cudaGetSymbolAddress((void**)&Vt,  g_Vt);
    cudaGetSymbolAddress((void**)&Oh,  g_Oh);
    cudaGetSymbolAddress((void**)&Eh,  g_Eh);
    cudaGetSymbolAddress((void**)&Iv,  g_inv);

    cudaFuncSetAttribute(hgemm_qkv, cudaFuncAttributeMaxDynamicSharedMemorySize, HG_SMEM);
    cudaFuncSetAttribute(hgemm_out, cudaFuncAttributeMaxDynamicSharedMemorySize, HG_SMEM);
    cudaFuncSetAttribute(qk_sums,   cudaFuncAttributeMaxDynamicSharedMemorySize, QKS_SMEM);
    cudaFuncSetAttribute(pv_fused,  cudaFuncAttributeMaxDynamicSharedMemorySize, PV_SMEM);

    dim3 gPrep(32, 32, 5);
    prep<<<gPrep, 256>>>(x, Wq, Wk, Wv, Wo, Xh, WqT, WkT, WvT, WoT);

    dim3 gQKV(8, 32, 3);
    hgemm_qkv<<<gQKV, 512, HG_SMEM>>>(Xh, WqT, WkT, WvT, Qh, Kh, Vt);

    dim3 gQK(8, BB * HH);
    qk_sums<<<gQK, 512, QKS_SMEM>>>(Qh, Kh, Eh, Iv);

    dim3 gPV(NN / 128, HH, BB);
    pv_fused<<<gPV, 256, PV_SMEM>>>(Eh, attn, Vt, Iv, Oh);

    dim3 gOut(8, 32);
    hgemm_out<<<gOut, 512, HG_SMEM>>>(Oh, WoT, out, bo);
}

// round 17
// speedup vs baseline: 2.0578x; 1.1740x over previous
#include <cuda_runtime.h>
#include <cuda_fp16.h>
#include <cstdint>
#include <cstddef>

#define BB   4
#define NN   1024
#define DIMC 1024
#define HH   16
#define DHD  64

// Scratch (no cudaMalloc allowed)
__device__ __half g_Xh [(size_t)BB * NN * DIMC];
__device__ __half g_WqT[(size_t)DIMC * DIMC];
__device__ __half g_WkT[(size_t)DIMC * DIMC];
__device__ __half g_WvT[(size_t)DIMC * DIMC];
__device__ __half g_WoT[(size_t)DIMC * DIMC];
__device__ __half g_Qh [(size_t)BB * NN * DIMC];
__device__ __half g_Kh [(size_t)BB * NN * DIMC];
__device__ __half g_Vt [(size_t)BB * DIMC * NN];   // [b*1024 + d][j]
__device__ __half g_Oh [(size_t)BB * NN * DIMC];
__device__ __half g_Eh [(size_t)BB * HH * NN * NN]; // unnormalized exp(S), fp16
__device__ float  g_inv[(size_t)BB * HH * NN];     // 1/rowsum

__device__ __forceinline__ void cp16(void* smem, const void* gmem) {
    uint32_t s = (uint32_t)__cvta_generic_to_shared(smem);
    asm volatile("cp.async.cg.shared.global [%0], [%1], 16;" :: "r"(s), "l"(gmem));
}
__device__ __forceinline__ void cp_commit() { asm volatile("cp.async.commit_group;"); }
__device__ __forceinline__ void cp_wait1()  { asm volatile("cp.async.wait_group 1;"); }
__device__ __forceinline__ void cp_wait2()  { asm volatile("cp.async.wait_group 2;"); }

#define MMA_F16(d, a0, a1, a2, a3, b0, b1)                                  \
    asm volatile(                                                           \
        "mma.sync.aligned.m16n8k16.row.col.f32.f16.f16.f32 "                \
        "{%0,%1,%2,%3}, {%4,%5,%6,%7}, {%8,%9}, {%0,%1,%2,%3};"             \
        : "+f"(d[0]), "+f"(d[1]), "+f"(d[2]), "+f"(d[3])                    \
        : "r"(a0), "r"(a1), "r"(a2), "r"(a3), "r"(b0), "r"(b1))

__device__ __forceinline__ void ldm4(uint32_t* r, const __half* p) {
    uint32_t a = (uint32_t)__cvta_generic_to_shared(p);
    asm volatile("ldmatrix.sync.aligned.m8n8.x4.shared.b16 {%0,%1,%2,%3}, [%4];"
        : "=r"(r[0]), "=r"(r[1]), "=r"(r[2]), "=r"(r[3]) : "r"(a));
}

__device__ __forceinline__ uint32_t h2u(__half2 h) {
    return *reinterpret_cast<uint32_t*>(&h);
}

// Scale a packed half2 by an fp32 factor with fp32 intermediate precision.
__device__ __forceinline__ uint32_t scale_h2(uint32_t u, float f) {
    __half2 h = *reinterpret_cast<__half2*>(&u);
    float2 fv = __half22float2(h);
    return h2u(__floats2half2_rn(fv.x * f, fv.y * f));
}

// ---------------------------------------------------------------------------
// prep: z=0: Xh = half(x); z=1..4: Wt[n][k] = half(W[k][n]).
// ---------------------------------------------------------------------------
__global__ __launch_bounds__(256) void prep(
    const float* __restrict__ x,
    const float* __restrict__ Wq, const float* __restrict__ Wk,
    const float* __restrict__ Wv, const float* __restrict__ Wo,
    __half* __restrict__ xh,
    __half* __restrict__ qt, __half* __restrict__ kt,
    __half* __restrict__ vt, __half* __restrict__ ot)
{
    int z = blockIdx.z;
    if (z == 0) {
        int bid = blockIdx.y * 32 + blockIdx.x;
        #pragma unroll
        for (int k = 0; k < 4; k++) {
            int i = bid * 1024 + k * 256 + threadIdx.x;
            float4 v = ((const float4*)x)[i];
            uint2 u;
            u.x = h2u(__floats2half2_rn(v.x, v.y));
            u.y = h2u(__floats2half2_rn(v.z, v.w));
            ((uint2*)xh)[i] = u;
        }
        return;
    }
    __shared__ float tile[32][33];
    const float* W = (z == 1) ? Wq : (z == 2) ? Wk : (z == 3) ? Wv : Wo;
    __half*      T = (z == 1) ? qt : (z == 2) ? kt : (z == 3) ? vt : ot;
    int bx = blockIdx.x * 32, by = blockIdx.y * 32;
    int tx = threadIdx.x & 31, ty = threadIdx.x >> 5;
    #pragma unroll
    for (int r = 0; r < 32; r += 8)
        tile[ty + r][tx] = W[(size_t)(by + ty + r) * DIMC + bx + tx];
    __syncthreads();
    #pragma unroll
    for (int r = 0; r < 32; r += 8)
        T[(size_t)(bx + ty + r) * DIMC + by + tx] = __float2half_rn(tile[tx][ty + r]);
}

// ---------------------------------------------------------------------------
// fp16 GEMM: C = A[M,K] @ Bt[N,K]^T. 128x128 tile, BK=64 halfs, 512 threads
// (16 warps, 4m x 4n, warp tile 32x32), 3-stage cp.async, ldmatrix operands.
// Stride 72 halfs: ldmatrix rows hit banks 9r mod 32 (all distinct).
// MODE 0: half out, scaled. MODE 1: float out + bias. MODE 2: Vt transposed.
// ---------------------------------------------------------------------------
#define HG_SMEM (3 * 2 * 128 * 72 * 2)   // 110592 B

template<int MODE>
__device__ __forceinline__ void hgemm_body(
    const __half* __restrict__ A, const __half* __restrict__ Bt,
    void* __restrict__ Cout, const float* __restrict__ bias,
    __half* __restrict__ Vt, float outScale, int K, int Nc)
{
    extern __shared__ __half smh[];
    __half* As = smh;             // [3][128][72]
    __half* Bs = smh + 3 * 9216;  // [3][128][72]

    const int t     = threadIdx.x;
    const int wid   = t >> 5, lane = t & 31;
    const int group = lane >> 2, tig = lane & 3;
    const int wm    = (wid & 3) * 32;
    const int wn    = (wid >> 2) * 32;
    const int m0    = blockIdx.y * 128;
    const int n0    = blockIdx.x * 128;

    const int la  = (lane & 15), lka = (lane >> 4) * 8;
    const int lb  = (lane & 7) + (lane >> 4) * 8;
    const int lkb = ((lane >> 3) & 1) * 8;

    auto load_stage = [&](int s, int k0) {
        __half* Ad = As + s * 9216;
        __half* Bd = Bs + s * 9216;
        #pragma unroll
        for (int l = 0; l < 2; l++) {
            int i = l * 512 + t;
            int r = i >> 3, c8 = (i & 7) * 8;
            cp16(Ad + r * 72 + c8, A  + (size_t)(m0 + r) * K + k0 + c8);
            cp16(Bd + r * 72 + c8, Bt + (size_t)(n0 + r) * K + k0 + c8);
        }
    };

    float acc[2][4][4] = {};
    load_stage(0, 0);  cp_commit();
    load_stage(1, 64); cp_commit();

    int s = 0;
    for (int k0 = 0; k0 < K; k0 += 64) {
        cp_wait1();
        __syncthreads();
        int s2 = (s >= 1) ? s - 1 : s + 2;
        if (k0 + 128 < K) load_stage(s2, k0 + 128);
        cp_commit();

        const __half* Ac = As + s * 9216;
        const __half* Bc = Bs + s * 9216;
        #pragma unroll
        for (int ks = 0; ks < 4; ks++) {
            int ko = ks * 16;
            uint32_t a[2][4], bb[2][4];
            ldm4(a[0],  Ac + (wm + la      ) * 72 + ko + lka);
            ldm4(a[1],  Ac + (wm + 16 + la ) * 72 + ko + lka);
            ldm4(bb[0], Bc + (wn + lb      ) * 72 + ko + lkb);
            ldm4(bb[1], Bc + (wn + 16 + lb ) * 72 + ko + lkb);
            #pragma unroll
            for (int np = 0; np < 2; np++) {
                #pragma unroll
                for (int mf = 0; mf < 2; mf++) {
                    MMA_F16(acc[mf][np * 2    ], a[mf][0], a[mf][1], a[mf][2], a[mf][3],
                            bb[np][0], bb[np][1]);
                    MMA_F16(acc[mf][np * 2 + 1], a[mf][0], a[mf][1], a[mf][2], a[mf][3],
                            bb[np][2], bb[np][3]);
                }
            }
        }
        s = (s == 2) ? 0 : s + 1;
        __syncthreads();
    }

    if (MODE == 2) {
        __half* st = smh;   // 128 x 132 halfs (33792 B, fits)
        #pragma unroll
        for (int mf = 0; mf < 2; mf++) {
            #pragma unroll
            for (int nf = 0; nf < 4; nf++) {
                int row = wm + mf * 16 + group;
                int col = wn + nf * 8 + tig * 2;
                st[(col    ) * 132 + row    ] = __float2half_rn(acc[mf][nf][0]);
                st[(col + 1) * 132 + row    ] = __float2half_rn(acc[mf][nf][1]);
                st[(col    ) * 132 + row + 8] = __float2half_rn(acc[mf][nf][2]);
                st[(col + 1) * 132 + row + 8] = __float2half_rn(acc[mf][nf][3]);
            }
        }
        __syncthreads();
        int b  = m0 >> 10;
        int j0 = m0 & 1023;
        #pragma unroll
        for (int p = 0; p < 16; p++) {
            int i = p * 512 + t;
            int d = i >> 6, c2 = (i & 63) * 2;
            uint32_t v = *(const uint32_t*)(st + d * 132 + c2);
            *(uint32_t*)(Vt + ((size_t)b * DIMC + n0 + d) * NN + j0 + c2) = v;
        }
        return;
    }

    #pragma unroll
    for (int mf = 0; mf < 2; mf++) {
        #pragma unroll
        for (int nf = 0; nf < 4; nf++) {
            int row = m0 + wm + mf * 16 + group;
            int col = n0 + wn + nf * 8 + tig * 2;
            if (MODE == 0) {
                __half* C = (__half*)Cout;
                *(__half2*)(C + (size_t)row       * Nc + col) =
                    __floats2half2_rn(acc[mf][nf][0] * outScale, acc[mf][nf][1] * outScale);
                *(__half2*)(C + (size_t)(row + 8) * Nc + col) =
                    __floats2half2_rn(acc[mf][nf][2] * outScale, acc[mf][nf][3] * outScale);
            } else {
                float* C = (float*)Cout;
                float bx = bias[col], by = bias[col + 1];
                *(float2*)(C + (size_t)row       * Nc + col) =
                    make_float2(acc[mf][nf][0] + bx, acc[mf][nf][1] + by);
                *(float2*)(C + (size_t)(row + 8) * Nc + col) =
                    make_float2(acc[mf][nf][2] + bx, acc[mf][nf][3] + by);
            }
        }
    }
}

__global__ __launch_bounds__(512) void hgemm_qkv(
    const __half* __restrict__ x,
    const __half* __restrict__ WqT, const __half* __restrict__ WkT,
    const __half* __restrict__ WvT,
    __half* __restrict__ Qo, __half* __restrict__ Ko, __half* __restrict__ Vt)
{
    if (blockIdx.z == 0)
        hgemm_body<0>(x, WqT, Qo, nullptr, nullptr, 0.125f, DIMC, HH * DHD);
    else if (blockIdx.z == 1)
        hgemm_body<0>(x, WkT, Ko, nullptr, nullptr, 1.0f, DIMC, HH * DHD);
    else
        hgemm_body<2>(x, WvT, nullptr, nullptr, Vt, 1.0f, DIMC, HH * DHD);
}

__global__ __launch_bounds__(512) void hgemm_out(
    const __half* __restrict__ A, const __half* __restrict__ WoT,
    float* __restrict__ C, const float* __restrict__ bias)
{
    hgemm_body<1>(A, WoT, C, bias, nullptr, 1.0f, DIMC, DIMC);
}

// ---------------------------------------------------------------------------
// qk_sums: per (m-tile 64, head): S = Qs @ K^T via f16 MMA (ldmatrix);
// stores E = exp(S) fp16 + 1/rowsum. 256 threads (8 warps: 2m x 4n),
// double-buffered cp.async 128-col K chunks. 3 CTAs/SM.
// ---------------------------------------------------------------------------
#define QKS_SMEM ((64 * 88 + 2 * 128 * 88) * 2)   // 56320 B

__global__ __launch_bounds__(256) void qk_sums(
    const __half* __restrict__ Q, const __half* __restrict__ Kt,
    __half* __restrict__ Eh, float* __restrict__ inv)
{
    extern __shared__ __half smq[];
    __half* Qs = smq;                // [64][88]
    __half* Ks = smq + 64 * 88;      // [2][128][88]
    __shared__ float rowpart[64][4];

    const int t     = threadIdx.x;
    const int wid   = t >> 5, lane = t & 31;
    const int group = lane >> 2, tig = lane & 3;
    const int wm    = (wid & 1) * 32;
    const int wn    = (wid >> 1) * 32;
    const int m0    = blockIdx.x * 64;
    const int bh    = blockIdx.y;
    const int b     = bh >> 4, h = bh & 15;
    const size_t base = (size_t)b * NN * DIMC + (size_t)h * DHD;

    const int lb  = (lane & 7) + (lane >> 4) * 8;
    const int lkb = ((lane >> 3) & 1) * 8;

    auto loadK = [&](int buf, int c) {
        __half* Td = Ks + buf * (128 * 88);
        #pragma unroll
        for (int p = 0; p < 4; p++) {
            int i = p * 256 + t;
            int r = i >> 3, c8 = (i & 7) * 8;
            cp16(Td + r * 88 + c8, Kt + base + (size_t)(c * 128 + r) * DIMC + c8);
        }
    };

    #pragma unroll
    for (int l = 0; l < 2; l++) {
        int i = l * 256 + t;
        int r = i >> 3, c8 = (i & 7) * 8;
        cp16(Qs + r * 88 + c8, Q + base + (size_t)(m0 + r) * DIMC + c8);
    }
    cp_commit();
    loadK(0, 0); cp_commit();
    loadK(1, 1); cp_commit();

    cp_wait2();
    __syncthreads();

    uint32_t qa[2][4][4];
    {
        const int la  = (lane & 15), lka = (lane >> 4) * 8;
        #pragma unroll
        for (int ks = 0; ks < 4; ks++) {
            int ko = ks * 16;
            ldm4(qa[0][ks], Qs + (wm + la     ) * 88 + ko + lka);
            ldm4(qa[1][ks], Qs + (wm + 16 + la) * 88 + ko + lka);
        }
    }

    float sr[4] = {0.f, 0.f, 0.f, 0.f};

    for (int c = 0; c < 8; c++) {
        cp_wait1();
        __syncthreads();

        const __half* Tc = Ks + (c & 1) * (128 * 88);
        float acc[2][4][4] = {};
        #pragma unroll
        for (int ks = 0; ks < 4; ks++) {
            int ko = ks * 16;
            uint32_t bb[2][4];
            ldm4(bb[0], Tc + (wn + lb     ) * 88 + ko + lkb);
            ldm4(bb[1], Tc + (wn + 16 + lb) * 88 + ko + lkb);
            #pragma unroll
            for (int np = 0; np < 2; np++) {
                #pragma unroll
                for (int mf = 0; mf < 2; mf++) {
                    MMA_F16(acc[mf][np * 2    ], qa[mf][ks][0], qa[mf][ks][1],
                            qa[mf][ks][2], qa[mf][ks][3], bb[np][0], bb[np][1]);
                    MMA_F16(acc[mf][np * 2 + 1], qa[mf][ks][0], qa[mf][ks][1],
                            qa[mf][ks][2], qa[mf][ks][3], bb[np][2], bb[np][3]);
                }
            }
        }

        __syncthreads();
        if (c < 6) loadK(c & 1, c + 2);
        cp_commit();

        __half* Sb = Eh + ((size_t)bh * NN + m0) * NN + c * 128;
        #pragma unroll
        for (int mf = 0; mf < 2; mf++) {
            #pragma unroll
            for (int nf = 0; nf < 4; nf++) {
                float e0 = __expf(acc[mf][nf][0]);
                float e1 = __expf(acc[mf][nf][1]);
                float e2 = __expf(acc[mf][nf][2]);
                float e3 = __expf(acc[mf][nf][3]);
                sr[mf * 2    ] += e0 + e1;
                sr[mf * 2 + 1] += e2 + e3;
                int row = wm + mf * 16 + group;
                int col = wn + nf * 8 + tig * 2;
                *(__half2*)(Sb + (size_t)row       * NN + col) = __floats2half2_rn(e0, e1);
                *(__half2*)(Sb + (size_t)(row + 8) * NN + col) = __floats2half2_rn(e2, e3);
            }
        }
    }

    #pragma unroll
    for (int i = 0; i < 4; i++) {
        sr[i] += __shfl_xor_sync(0xffffffffu, sr[i], 1);
        sr[i] += __shfl_xor_sync(0xffffffffu, sr[i], 2);
    }
    if (tig == 0) {
        #pragma unroll
        for (int mf = 0; mf < 2; mf++) {
            rowpart[wm + mf * 16 + group    ][wid >> 1] = sr[mf * 2    ];
            rowpart[wm + mf * 16 + group + 8][wid >> 1] = sr[mf * 2 + 1];
        }
    }
    __syncthreads();
    if (t < 64) {
        float ssum = rowpart[t][0] + rowpart[t][1] + rowpart[t][2] + rowpart[t][3];
        inv[(size_t)bh * NN + m0 + t] = 1.f / ssum;
    }
}

// ---------------------------------------------------------------------------
// pv_fused: O = (E * inv) @ V ; writes normalized attn (fp32) from staged
// fp16 E. 128x64 tile, 256 threads (8 warps: 4m x 2n), BK=32, 3-stage
// cp.async, scalar fragment loads (stride 40 halfs: conflict-free).
// ---------------------------------------------------------------------------
#define PV_SMEM (3 * (128 * 40 + 64 * 40) * 2)   // 46080 B

__global__ __launch_bounds__(256) void pv_fused(
    const __half* __restrict__ Eh, float* __restrict__ attn,
    const __half* __restrict__ Vt,
    const float* __restrict__ inv, __half* __restrict__ Oh)
{
    extern __shared__ __half smv[];
    __half* As = smv;                  // [3][128][40]
    __half* Bs = smv + 3 * 128 * 40;   // [3][64][40]

    const int t     = threadIdx.x;
    const int wid   = t >> 5, lane = t & 31;
    const int group = lane >> 2, tig = lane & 3;
    const int wm    = (wid & 3) * 32;
    const int wn    = (wid >> 2) * 32;
    const int m0    = blockIdx.x * 128;
    const int h     = blockIdx.y, b = blockIdx.z;

    const size_t rowbase = ((size_t)b * HH + h) * NN + m0;
    const __half* Eb  = Eh + rowbase * NN;
    float*        Pb  = attn + rowbase * NN;
    const __half* Vtb = Vt + ((size_t)b * DIMC + h * DHD) * NN;
    __half*       Ob  = Oh + (size_t)b * NN * DIMC + (size_t)h * DHD;

    float fi[4];
    #pragma unroll
    for (int mf = 0; mf < 2; mf++) {
        fi[mf * 2    ] = inv[rowbase + wm + mf * 16 + group    ];
        fi[mf * 2 + 1] = inv[rowbase + wm + mf * 16 + group + 8];
    }
    float wi[4];
    #pragma unroll
    for (int l = 0; l < 4; l++) wi[l] = inv[rowbase + ((l * 256 + t) >> 3)];

    auto load_stage = [&](int s, int k0) {
        __half* Ad = As + s * (128 * 40);
        __half* Bd = Bs + s * (64 * 40);
        #pragma unroll
        for (int l = 0; l < 2; l++) {
            int i = l * 256 + t;
            int r = i >> 2, c8 = (i & 3) * 8;
            cp16(Ad + r * 40 + c8, Eb + (size_t)r * NN + k0 + c8);
        }
        {
            int r = t >> 2, c8 = (t & 3) * 8;
            cp16(Bd + r * 40 + c8, Vtb + (size_t)r * NN + k0 + c8);
        }
    };

    float acc[2][4][4] = {};

    load_stage(0, 0);  cp_commit();
    load_stage(1, 32); cp_commit();

    int s = 0;
    for (int k0 = 0; k0 < NN; k0 += 32) {
        cp_wait1();
        __syncthreads();
        int s2 = (s >= 1) ? s - 1 : s + 2;
        if (k0 + 64 < NN) load_stage(s2, k0 + 64);
        cp_commit();

        const __half* Ac = As + s * (128 * 40);
        const __half* Bc = Bs + s * (64 * 40);

        // normalized attn write (fp32) from staged fp16 E: 128 rows x 32 cols
        #pragma unroll
        for (int l = 0; l < 4; l++) {
            int i = l * 256 + t;
            int r = i >> 3, k4 = (i & 7) * 4;
            const __half* src = Ac + r * 40 + k4;
            __half2 h0 = *(const __half2*)(src);
            __half2 h1 = *(const __half2*)(src + 2);
            float wl = wi[l];
            float4 v;
            v.x = __low2float(h0) * wl; v.y = __high2float(h0) * wl;
            v.z = __low2float(h1) * wl; v.w = __high2float(h1) * wl;
            *(float4*)(Pb + (size_t)r * NN + k0 + k4) = v;
        }

        #pragma unroll
        for (int ks = 0; ks < 2; ks++) {
            int ko = ks * 16;
            uint32_t a[2][4];
            #pragma unroll
            for (int mf = 0; mf < 2; mf++) {
                const __half* Ar = Ac + (wm + mf * 16 + group) * 40 + 2 * tig + ko;
                float f0 = fi[mf * 2], f1 = fi[mf * 2 + 1];
                a[mf][0] = scale_h2(*(const uint32_t*)(Ar      ), f0);
                a[mf][1] = scale_h2(*(const uint32_t*)(Ar + 320), f1);   // row +8
                a[mf][2] = scale_h2(*(const uint32_t*)(Ar +   8), f0);   // k +8
                a[mf][3] = scale_h2(*(const uint32_t*)(Ar + 328), f1);
            }
            #pragma unroll
            for (int nf = 0; nf < 4; nf++) {
                const __half* Br = Bc + (wn + nf * 8 + group) * 40 + 2 * tig + ko;
                uint32_t b0 = *(const uint32_t*)(Br);
                uint32_t b1 = *(const uint32_t*)(Br + 8);
                #pragma unroll
                for (int mf = 0; mf < 2; mf++)
                    MMA_F16(acc[mf][nf], a[mf][0], a[mf][1], a[mf][2], a[mf][3], b0, b1);
            }
        }
        s = (s == 2) ? 0 : s + 1;
        __syncthreads();
    }

    #pragma unroll
    for (int mf = 0; mf < 2; mf++) {
        #pragma unroll
        for (int nf = 0; nf < 4; nf++) {
            int row = m0 + wm + mf * 16 + group;
            int col = wn + nf * 8 + tig * 2;
            *(__half2*)(Ob + (size_t)row       * DIMC + col) =
                __floats2half2_rn(acc[mf][nf][0], acc[mf][nf][1]);
            *(__half2*)(Ob + (size_t)(row + 8) * DIMC + col) =
                __floats2half2_rn(acc[mf][nf][2], acc[mf][nf][3]);
        }
    }
}

// ---------------------------------------------------------------------------
extern "C" void kernel_launch(void* const* d_in, const int* in_sizes, int n_in,
                              void* d_out, int out_size)
{
    const float* x  = (const float*)d_in[0];
    const float* Wq = (const float*)d_in[1];
    const float* Wk = (const float*)d_in[2];
    const float* Wv = (const float*)d_in[3];
    const float* Wo = (const float*)d_in[4];
    const float* bo = (const float*)d_in[5];

    float* out  = (float*)d_out;
    float* attn = out + (size_t)BB * NN * DIMC;

    __half *Xh, *WqT, *WkT, *WvT, *WoT, *Qh, *Kh, *Vt, *Oh, *Eh;
    float* Iv;
    cudaGetSymbolAddress((void**)&Xh,  g_Xh);
    cudaGetSymbolAddress((void**)&WqT, g_WqT);
    cudaGetSymbolAddress((void**)&WkT, g_WkT);
    cudaGetSymbolAddress((void**)&WvT, g_WvT);
    cudaGetSymbolAddress((void**)&WoT, g_WoT);
    cudaGetSymbolAddress((void**)&Qh,  g_Qh);
    cudaGetSymbolAddress((void**)&Kh,  g_Kh);
    cudaGetSymbolAddress((void**)&Vt,  g_Vt);
    cudaGetSymbolAddress((void**)&Oh,  g_Oh);
    cudaGetSymbolAddress((void**)&Eh,  g_Eh);
    cudaGetSymbolAddress((void**)&Iv,  g_inv);

    cudaFuncSetAttribute(hgemm_qkv, cudaFuncAttributeMaxDynamicSharedMemorySize, HG_SMEM);
    cudaFuncSetAttribute(hgemm_out, cudaFuncAttributeMaxDynamicSharedMemorySize, HG_SMEM);
    cudaFuncSetAttribute(qk_sums,   cudaFuncAttributeMaxDynamicSharedMemorySize, QKS_SMEM);
    cudaFuncSetAttribute(pv_fused,  cudaFuncAttributeMaxDynamicSharedMemorySize, PV_SMEM);

    dim3 gPrep(32, 32, 5);
    prep<<<gPrep, 256>>>(x, Wq, Wk, Wv, Wo, Xh, WqT, WkT, WvT, WoT);

    dim3 gQKV(8, 32, 3);
    hgemm_qkv<<<gQKV, 512, HG_SMEM>>>(Xh, WqT, WkT, WvT, Qh, Kh, Vt);

    dim3 gQK(16, BB * HH);
    qk_sums<<<gQK, 256, QKS_SMEM>>>(Qh, Kh, Eh, Iv);

    dim3 gPV(NN / 128, HH, BB);
    pv_fused<<<gPV, 256, PV_SMEM>>>(Eh, attn, Vt, Iv, Oh);

    dim3 gOut(8, 32);
    hgemm_out<<<gOut, 512, HG_SMEM>>>(Oh, WoT, out, bo);
}